// round 13
// baseline (speedup 1.0000x reference)
#include <cuda_runtime.h>
#include <cuda_bf16.h>

#define BB 16
#define RR 1024
#define TT 512
#define DD 1024
#define HH 1024

// ---------------------------------------------------------------------------
// Scratch (device globals — allocations are forbidden)
// ---------------------------------------------------------------------------
__device__ __nv_bfloat16 g_Wr_h[DD * HH], g_Wr_l[DD * HH];
__device__ __nv_bfloat16 g_Wq_h[DD * HH], g_Wq_l[DD * HH];
__device__ __nv_bfloat16 g_M2_h[DD * DD], g_M2_l[DD * DD];       // M2[d,e] = sum_h Wr[d,h]Wq[e,h]
__device__ __nv_bfloat16 g_rf_h[(size_t)BB * RR * DD], g_rf_l[(size_t)BB * RR * DD];
__device__ __nv_bfloat16 g_qe_h[(size_t)BB * TT * DD], g_qe_l[(size_t)BB * TT * DD];
__device__ __nv_bfloat16 g_qe2_h[(size_t)BB * TT * DD], g_qe2_l[(size_t)BB * TT * DD]; // qe*Ws2
__device__ __nv_bfloat16 g_Nt_h[(size_t)BB * TT * DD], g_Nt_l[(size_t)BB * TT * DD];   // Nt[b][t,d]
__device__ float4        g_part[(size_t)BB * RR * 8];   // (m, den, num, pad) per t-slice of 64
__device__ float         g_v[DD];
__device__ float         g_qv[BB * TT];
__device__ float         g_y1[BB * TT];
__device__ float         g_rd0[BB * RR];

// ---------------------------------------------------------------------------
// PTX helpers (sm_80-level features only: ldmatrix, cp.async, mma.sync)
// ---------------------------------------------------------------------------
__device__ __forceinline__ unsigned smem_u32(const void* p) {
    unsigned a;
    asm("{ .reg .u64 t; cvta.to.shared.u64 t, %1; cvt.u32.u64 %0, t; }" : "=r"(a) : "l"(p));
    return a;
}

#define CP_ASYNC16(dst, src) \
    asm volatile("cp.async.cg.shared.global [%0], [%1], 16;" :: "r"(dst), "l"(src))
#define CP_COMMIT() asm volatile("cp.async.commit_group;" ::: "memory")
#define CP_WAIT0()  asm volatile("cp.async.wait_group 0;" ::: "memory")
#define CP_WAIT1()  asm volatile("cp.async.wait_group 1;" ::: "memory")
#define CP_WAIT2()  asm volatile("cp.async.wait_group 2;" ::: "memory")

__device__ __forceinline__ void ldsm4(unsigned* r, unsigned addr) {
    asm volatile("ldmatrix.sync.aligned.m8n8.x4.shared.b16 {%0,%1,%2,%3}, [%4];"
                 : "=r"(r[0]), "=r"(r[1]), "=r"(r[2]), "=r"(r[3]) : "r"(addr));
}

__device__ __forceinline__ void mma_bf16(float* c, const unsigned* a, const unsigned* b) {
    asm volatile(
        "mma.sync.aligned.m16n8k16.row.col.f32.bf16.bf16.f32 "
        "{%0,%1,%2,%3}, {%4,%5,%6,%7}, {%8,%9}, {%0,%1,%2,%3};"
        : "+f"(c[0]), "+f"(c[1]), "+f"(c[2]), "+f"(c[3])
        : "r"(a[0]), "r"(a[1]), "r"(a[2]), "r"(a[3]), "r"(b[0]), "r"(b[1]));
}

__device__ __forceinline__ unsigned swz(unsigned off) {
    return off ^ ((off >> 3) & 0x70);
}

// ---------------------------------------------------------------------------
// Split-bf16 GEMM, CTA tile 64x128 (8 warps = 2M x 4N, warp tile 32x32).
// 3 terms: hh + hl + lh. K chunks of 64 bf16 (SW128), 3-stage cp.async.
// Split hi/lo bf16 output. Used for M2 and Nt.
// ---------------------------------------------------------------------------
__global__ void __launch_bounds__(256) gemm_mma1(
    const __nv_bfloat16* __restrict__ A0, const __nv_bfloat16* __restrict__ A1,
    const __nv_bfloat16* __restrict__ B0, const __nv_bfloat16* __restrict__ B1,
    __nv_bfloat16* __restrict__ Ch, __nv_bfloat16* __restrict__ Cl,
    int K, size_t sA, size_t sB, size_t sC, int ldc)
{
    constexpr unsigned TA = 64 * 128;     // 8 KB per A split tile
    constexpr unsigned TB = 128 * 128;    // 16 KB per B split tile
    constexpr unsigned STAGE = 2 * TA + 2 * TB;   // 48 KB

    extern __shared__ char smem[];
    const unsigned sbase = smem_u32(smem);

    const int tid = threadIdx.x;
    const int lid = tid & 31;
    const int wid = tid >> 5;
    const int wm = wid & 1;
    const int wn = wid >> 1;

    const size_t zb = blockIdx.z;
    const __nv_bfloat16* AP[2] = { A0 + zb * sA, A1 + zb * sA };
    const __nv_bfloat16* BP[2] = { B0 + zb * sB, B1 + zb * sB };
    const size_t rm0 = (size_t)blockIdx.y * 64;
    const size_t rn0 = (size_t)blockIdx.x * 128;
    const int NC = K >> 6;

    float c[2][4][4] = {};

    const int al_r  = lid & 15;
    const int al_k  = (lid >> 4) & 1;
    const int bl_r  = (lid & 7) + ((lid >> 4) << 3);
    const int bl_k  = (lid >> 3) & 1;

    auto load_stage = [&](int st, int ck) {
        const unsigned sdst = sbase + (unsigned)st * STAGE;
        const int k0 = ck << 6;
        #pragma unroll
        for (int sp = 0; sp < 2; sp++) {
            #pragma unroll
            for (int i = 0; i < 2; i++) {
                int idx = i * 256 + tid;
                int row = idx >> 3, g = idx & 7;
                const __nv_bfloat16* gs = AP[sp] + (rm0 + row) * (size_t)K + k0 + g * 8;
                unsigned d = sdst + (unsigned)sp * TA + swz((unsigned)(row * 128 + g * 16));
                CP_ASYNC16(d, gs);
            }
        }
        #pragma unroll
        for (int sp = 0; sp < 2; sp++) {
            #pragma unroll
            for (int i = 0; i < 4; i++) {
                int idx = i * 256 + tid;
                int row = idx >> 3, g = idx & 7;
                const __nv_bfloat16* gs = BP[sp] + (rn0 + row) * (size_t)K + k0 + g * 8;
                unsigned d = sdst + 2 * TA + (unsigned)sp * TB +
                             swz((unsigned)(row * 128 + g * 16));
                CP_ASYNC16(d, gs);
            }
        }
    };

    load_stage(0, 0); CP_COMMIT();
    load_stage(1, 1); CP_COMMIT();

    for (int ck = 0; ck < NC; ck++) {
        if (ck + 1 < NC) CP_WAIT1(); else CP_WAIT0();
        __syncthreads();
        if (ck + 2 < NC) {
            load_stage((ck + 2) % 3, ck + 2);
            CP_COMMIT();
        }

        const unsigned sb2 = sbase + (unsigned)(ck % 3) * STAGE;
        #pragma unroll
        for (int ks = 0; ks < 4; ks++) {
            unsigned af[2][2][4];
            unsigned bf[2][4][2];
            #pragma unroll
            for (int sp = 0; sp < 2; sp++) {
                #pragma unroll
                for (int mt = 0; mt < 2; mt++) {
                    unsigned addr = sb2 + (unsigned)sp * TA +
                        swz((unsigned)((wm * 32 + mt * 16 + al_r) * 128 + ks * 32 + al_k * 16));
                    ldsm4(af[sp][mt], addr);
                }
                #pragma unroll
                for (int np = 0; np < 2; np++) {
                    unsigned r[4];
                    unsigned addr = sb2 + 2 * TA + (unsigned)sp * TB +
                        swz((unsigned)((wn * 32 + np * 16 + bl_r) * 128 + ks * 32 + bl_k * 16));
                    ldsm4(r, addr);
                    bf[sp][2 * np][0] = r[0]; bf[sp][2 * np][1] = r[1];
                    bf[sp][2 * np + 1][0] = r[2]; bf[sp][2 * np + 1][1] = r[3];
                }
            }
            #pragma unroll
            for (int tm = 0; tm < 3; tm++) {
                const int i = (tm == 2) ? 1 : 0;
                const int j = (tm == 1) ? 1 : 0;
                #pragma unroll
                for (int mt = 0; mt < 2; mt++)
                    #pragma unroll
                    for (int nt = 0; nt < 4; nt++)
                        mma_bf16(c[mt][nt], af[i][mt], bf[j][nt]);
            }
        }
    }
    __syncthreads();

    const int qr = lid >> 2;
    const int qc = (lid & 3) * 2;
    #pragma unroll
    for (int mt = 0; mt < 2; mt++) {
        #pragma unroll
        for (int nt = 0; nt < 4; nt++) {
            size_t gr = rm0 + wm * 32 + mt * 16 + qr;
            int gc = (int)rn0 + wn * 32 + nt * 8 + qc;
            #pragma unroll
            for (int half = 0; half < 2; half++) {
                float v0 = c[mt][nt][2 * half + 0];
                float v1 = c[mt][nt][2 * half + 1];
                size_t o = zb * sC + (gr + half * 8) * (size_t)ldc + gc;
                __nv_bfloat162 hv, lv;
                hv.x = __float2bfloat16(v0);
                hv.y = __float2bfloat16(v1);
                lv.x = __float2bfloat16(v0 - __bfloat162float(hv.x));
                lv.y = __float2bfloat16(v1 - __bfloat162float(hv.y));
                *reinterpret_cast<__nv_bfloat162*>(Ch + o) = hv;
                *reinterpret_cast<__nv_bfloat162*>(Cl + o) = lv;
            }
        }
    }
}

// ---------------------------------------------------------------------------
// Dual-B GEMM with fused split-softmax epilogue. CTA tile 64x64,
// 4-stage cp.async pipeline (48 KB/stage). 8 warps = 2M x 4N, warp 32x16.
// c1 = rf@Nt^T, c2 = rf@qe2^T. Per row: partial softmax over 64 t-values;
// one float4 (m, den, num, 0) per (row, t-slice of 64).
// ---------------------------------------------------------------------------
__global__ void __launch_bounds__(256) gemm_dual(
    const __nv_bfloat16* __restrict__ A0, const __nv_bfloat16* __restrict__ A1,
    const __nv_bfloat16* __restrict__ B0, const __nv_bfloat16* __restrict__ B1,
    const __nv_bfloat16* __restrict__ C0, const __nv_bfloat16* __restrict__ C1,
    const float* __restrict__ qv, const float* __restrict__ y1,
    float4* __restrict__ part,
    int K, size_t sA, size_t sB)
{
    constexpr unsigned TA = 64 * 128;     // 8 KB
    constexpr unsigned TB = 64 * 128;     // 8 KB
    constexpr unsigned STAGE = 2 * TA + 4 * TB;   // 48 KB

    extern __shared__ char smem[];
    const unsigned sbase = smem_u32(smem);

    const int tid = threadIdx.x;
    const int lid = tid & 31;
    const int wid = tid >> 5;
    const int wm = wid & 1;        // M slab (32 rows)
    const int wn = wid >> 1;       // N slab (16 t-cols)

    const size_t zb = blockIdx.z;
    const __nv_bfloat16* AP[2] = { A0 + zb * sA, A1 + zb * sA };
    const __nv_bfloat16* BP[4] = { B0 + zb * sB, B1 + zb * sB,
                                   C0 + zb * sB, C1 + zb * sB };
    const size_t rm0 = (size_t)blockIdx.y * 64;
    const size_t rn0 = (size_t)blockIdx.x * 64;
    const int NC = K >> 6;

    float c1[2][2][4] = {};
    float c2[2][2][4] = {};

    const int al_r  = lid & 15;
    const int al_k  = (lid >> 4) & 1;
    const int bl_r  = (lid & 7) + ((lid >> 4) << 3);
    const int bl_k  = (lid >> 3) & 1;

    auto load_stage = [&](int st, int ck) {
        const unsigned sdst = sbase + (unsigned)st * STAGE;
        const int k0 = ck << 6;
        #pragma unroll
        for (int sp = 0; sp < 2; sp++) {
            #pragma unroll
            for (int i = 0; i < 2; i++) {
                int idx = i * 256 + tid;
                int row = idx >> 3, g = idx & 7;
                const __nv_bfloat16* gs = AP[sp] + (rm0 + row) * (size_t)K + k0 + g * 8;
                unsigned d = sdst + (unsigned)sp * TA + swz((unsigned)(row * 128 + g * 16));
                CP_ASYNC16(d, gs);
            }
        }
        #pragma unroll
        for (int t4 = 0; t4 < 4; t4++) {
            #pragma unroll
            for (int i = 0; i < 2; i++) {
                int idx = i * 256 + tid;
                int row = idx >> 3, g = idx & 7;
                const __nv_bfloat16* gs = BP[t4] + (rn0 + row) * (size_t)K + k0 + g * 8;
                unsigned d = sdst + 2 * TA + (unsigned)t4 * TB +
                             swz((unsigned)(row * 128 + g * 16));
                CP_ASYNC16(d, gs);
            }
        }
    };

    load_stage(0, 0); CP_COMMIT();
    load_stage(1, 1); CP_COMMIT();
    load_stage(2, 2); CP_COMMIT();

    for (int ck = 0; ck < NC; ck++) {
        if (ck + 2 < NC)      CP_WAIT2();
        else if (ck + 1 < NC) CP_WAIT1();
        else                  CP_WAIT0();
        __syncthreads();
        if (ck + 3 < NC) {
            load_stage((ck + 3) & 3, ck + 3);
            CP_COMMIT();
        }

        const unsigned sb2 = sbase + (unsigned)(ck & 3) * STAGE;
        #pragma unroll
        for (int ks = 0; ks < 4; ks++) {
            unsigned af[2][2][4];
            #pragma unroll
            for (int sp = 0; sp < 2; sp++)
                #pragma unroll
                for (int mt = 0; mt < 2; mt++) {
                    unsigned addr = sb2 + (unsigned)sp * TA +
                        swz((unsigned)((wm * 32 + mt * 16 + al_r) * 128 + ks * 32 + al_k * 16));
                    ldsm4(af[sp][mt], addr);
                }
            {
                unsigned bf[2][2][2];
                #pragma unroll
                for (int sp = 0; sp < 2; sp++) {
                    unsigned r[4];
                    unsigned addr = sb2 + 2 * TA + (unsigned)sp * TB +
                        swz((unsigned)((wn * 16 + bl_r) * 128 + ks * 32 + bl_k * 16));
                    ldsm4(r, addr);
                    bf[sp][0][0] = r[0]; bf[sp][0][1] = r[1];
                    bf[sp][1][0] = r[2]; bf[sp][1][1] = r[3];
                }
                #pragma unroll
                for (int tm = 0; tm < 3; tm++) {
                    const int i = (tm == 2) ? 1 : 0;
                    const int j = (tm == 1) ? 1 : 0;
                    #pragma unroll
                    for (int mt = 0; mt < 2; mt++)
                        #pragma unroll
                        for (int nt = 0; nt < 2; nt++)
                            mma_bf16(c1[mt][nt], af[i][mt], bf[j][nt]);
                }
            }
            {
                unsigned bf[2][2][2];
                #pragma unroll
                for (int sp = 0; sp < 2; sp++) {
                    unsigned r[4];
                    unsigned addr = sb2 + 2 * TA + (unsigned)(2 + sp) * TB +
                        swz((unsigned)((wn * 16 + bl_r) * 128 + ks * 32 + bl_k * 16));
                    ldsm4(r, addr);
                    bf[sp][0][0] = r[0]; bf[sp][0][1] = r[1];
                    bf[sp][1][0] = r[2]; bf[sp][1][1] = r[3];
                }
                #pragma unroll
                for (int tm = 0; tm < 3; tm++) {
                    const int i = (tm == 2) ? 1 : 0;
                    const int j = (tm == 1) ? 1 : 0;
                    #pragma unroll
                    for (int mt = 0; mt < 2; mt++)
                        #pragma unroll
                        for (int nt = 0; nt < 2; nt++)
                            mma_bf16(c2[mt][nt], af[i][mt], bf[j][nt]);
                }
            }
        }
        __syncthreads();
    }

    // ---- Fused split-softmax epilogue over this CTA's 64 t-values ----
    const int qr = lid >> 2;
    const int qc = (lid & 3) * 2;
    const size_t boff = zb * TT;
    const int tbase = (int)rn0 + wn * 16;

    float2 qvv[2], y1v[2];
    #pragma unroll
    for (int nt = 0; nt < 2; nt++) {
        int t0 = tbase + nt * 8 + qc;
        qvv[nt] = *reinterpret_cast<const float2*>(qv + boff + t0);
        y1v[nt] = *reinterpret_cast<const float2*>(y1 + boff + t0);
    }

    float* sp = reinterpret_cast<float*>(smem);   // [64 rows][4 wn][3] = 3 KB

    #pragma unroll
    for (int mt = 0; mt < 2; mt++) {
        #pragma unroll
        for (int half = 0; half < 2; half++) {
            float sv[4];
            float m = -1e30f;
            #pragma unroll
            for (int nt = 0; nt < 2; nt++) {
                sv[2 * nt]     = c1[mt][nt][2 * half]     + qvv[nt].x;
                sv[2 * nt + 1] = c1[mt][nt][2 * half + 1] + qvv[nt].y;
                m = fmaxf(m, fmaxf(sv[2 * nt], sv[2 * nt + 1]));
            }
            float den = 0.f, num = 0.f;
            #pragma unroll
            for (int nt = 0; nt < 2; nt++) {
                float e0 = __expf(sv[2 * nt] - m);
                float e1 = __expf(sv[2 * nt + 1] - m);
                den += e0 + e1;
                num = fmaf(e0, y1v[nt].x + c2[mt][nt][2 * half], num);
                num = fmaf(e1, y1v[nt].y + c2[mt][nt][2 * half + 1], num);
            }
            // merge across the 4 qc-lanes (lid^1, lid^2)
            #pragma unroll
            for (int o = 1; o <= 2; o <<= 1) {
                float mo = __shfl_xor_sync(0xffffffffu, m, o);
                float dn = __shfl_xor_sync(0xffffffffu, den, o);
                float no = __shfl_xor_sync(0xffffffffu, num, o);
                float mn = fmaxf(m, mo);
                float sa = __expf(m - mn), sb = __expf(mo - mn);
                den = den * sa + dn * sb;
                num = num * sa + no * sb;
                m = mn;
            }
            if ((lid & 3) == 0) {
                int lr = wm * 32 + mt * 16 + qr + half * 8;
                sp[(lr * 4 + wn) * 3 + 0] = m;
                sp[(lr * 4 + wn) * 3 + 1] = den;
                sp[(lr * 4 + wn) * 3 + 2] = num;
            }
        }
    }
    __syncthreads();
    if (tid < 64) {
        float m = -1e30f;
        #pragma unroll
        for (int w = 0; w < 4; w++) m = fmaxf(m, sp[(tid * 4 + w) * 3]);
        float den = 0.f, num = 0.f;
        #pragma unroll
        for (int w = 0; w < 4; w++) {
            float s = __expf(sp[(tid * 4 + w) * 3] - m);
            den = fmaf(sp[(tid * 4 + w) * 3 + 1], s, den);
            num = fmaf(sp[(tid * 4 + w) * 3 + 2], s, num);
        }
        size_t row = zb * RR + rm0 + tid;
        part[row * 8 + blockIdx.x] = make_float4(m, den, num, 0.f);
    }
}

// ---------------------------------------------------------------------------
// Finalize: merge 8 softmax partials per row; out = rd0 + num/den + bs
// ---------------------------------------------------------------------------
__global__ void __launch_bounds__(256) finalize_k(
    const float4* __restrict__ part, const float* __restrict__ rd0,
    const float* __restrict__ bs, float* __restrict__ out)
{
    int i = blockIdx.x * 256 + threadIdx.x;
    float4 p[8];
    #pragma unroll
    for (int w = 0; w < 8; w++) p[w] = part[(size_t)i * 8 + w];
    float m = -1e30f;
    #pragma unroll
    for (int w = 0; w < 8; w++) m = fmaxf(m, p[w].x);
    float den = 0.f, num = 0.f;
    #pragma unroll
    for (int w = 0; w < 8; w++) {
        float s = __expf(p[w].x - m);
        den = fmaf(p[w].y, s, den);
        num = fmaf(p[w].z, s, num);
    }
    out[i] = rd0[i] + num / den + bs[0];
}

// ---------------------------------------------------------------------------
// fp32 -> 2-way bf16 split (elementwise, vectorized) — for weights
// ---------------------------------------------------------------------------
__global__ void __launch_bounds__(256) split2_k(
    const float4* __restrict__ x, __nv_bfloat16* __restrict__ h,
    __nv_bfloat16* __restrict__ l, int n4)
{
    for (int i = blockIdx.x * blockDim.x + threadIdx.x; i < n4;
         i += gridDim.x * blockDim.x) {
        float4 v = x[i];
        float a[4] = {v.x, v.y, v.z, v.w};
        __nv_bfloat16 hh[4], ll[4];
        #pragma unroll
        for (int k = 0; k < 4; k++) {
            hh[k] = __float2bfloat16(a[k]);
            ll[k] = __float2bfloat16(a[k] - __bfloat162float(hh[k]));
        }
        __nv_bfloat162 p0, p1;
        p0.x = hh[0]; p0.y = hh[1]; p1.x = hh[2]; p1.y = hh[3];
        reinterpret_cast<__nv_bfloat162*>(h)[2 * i] = p0;
        reinterpret_cast<__nv_bfloat162*>(h)[2 * i + 1] = p1;
        p0.x = ll[0]; p0.y = ll[1]; p1.x = ll[2]; p1.y = ll[3];
        reinterpret_cast<__nv_bfloat162*>(l)[2 * i] = p0;
        reinterpret_cast<__nv_bfloat162*>(l)[2 * i + 1] = p1;
    }
}

// ---------------------------------------------------------------------------
// region prep: one CTA per (b,r) row. Writes rf_h/rf_l; computes rd0 = row.Ws0.
// ---------------------------------------------------------------------------
__global__ void __launch_bounds__(256) region_prep_k(
    const float* __restrict__ region, const float* __restrict__ Ws0,
    __nv_bfloat16* __restrict__ rf_h, __nv_bfloat16* __restrict__ rf_l,
    float* __restrict__ rd0)
{
    size_t row = blockIdx.x;
    int t = threadIdx.x;
    float4 a = *reinterpret_cast<const float4*>(region + row * DD + t * 4);
    float4 w = *reinterpret_cast<const float4*>(Ws0 + t * 4);

    __nv_bfloat162 h0, h1, l0, l1;
    h0.x = __float2bfloat16(a.x); h0.y = __float2bfloat16(a.y);
    h1.x = __float2bfloat16(a.z); h1.y = __float2bfloat16(a.w);
    l0.x = __float2bfloat16(a.x - __bfloat162float(h0.x));
    l0.y = __float2bfloat16(a.y - __bfloat162float(h0.y));
    l1.x = __float2bfloat16(a.z - __bfloat162float(h1.x));
    l1.y = __float2bfloat16(a.w - __bfloat162float(h1.y));
    reinterpret_cast<__nv_bfloat162*>(rf_h + row * DD)[2 * t] = h0;
    reinterpret_cast<__nv_bfloat162*>(rf_h + row * DD)[2 * t + 1] = h1;
    reinterpret_cast<__nv_bfloat162*>(rf_l + row * DD)[2 * t] = l0;
    reinterpret_cast<__nv_bfloat162*>(rf_l + row * DD)[2 * t + 1] = l1;

    float p = a.x * w.x + a.y * w.y + a.z * w.z + a.w * w.w;
    __shared__ float red[8];
    #pragma unroll
    for (int o = 16; o; o >>= 1) p += __shfl_xor_sync(0xffffffffu, p, o);
    if ((t & 31) == 0) red[t >> 5] = p;
    __syncthreads();
    if (t == 0) {
        float s = 0.f;
        #pragma unroll
        for (int i = 0; i < 8; i++) s += red[i];
        rd0[row] = s;
    }
}

// ---------------------------------------------------------------------------
// query prep: one CTA per (b,t) row. Writes qe_h/l and qe2_h/l (= qe*Ws2);
// computes qv = row.v and y1 = row.Ws1.
// ---------------------------------------------------------------------------
__global__ void __launch_bounds__(256) query_prep_k(
    const float* __restrict__ query, const float* __restrict__ v,
    const float* __restrict__ Ws1, const float* __restrict__ Ws2,
    __nv_bfloat16* __restrict__ qe_h, __nv_bfloat16* __restrict__ qe_l,
    __nv_bfloat16* __restrict__ qe2_h, __nv_bfloat16* __restrict__ qe2_l,
    float* __restrict__ qv, float* __restrict__ y1)
{
    size_t row = blockIdx.x;
    int t = threadIdx.x;
    float4 a = *reinterpret_cast<const float4*>(query + row * DD + t * 4);
    float4 vv = *reinterpret_cast<const float4*>(v + t * 4);
    float4 w1 = *reinterpret_cast<const float4*>(Ws1 + t * 4);
    float4 w2 = *reinterpret_cast<const float4*>(Ws2 + t * 4);

    __nv_bfloat162 h0, h1, l0, l1;
    h0.x = __float2bfloat16(a.x); h0.y = __float2bfloat16(a.y);
    h1.x = __float2bfloat16(a.z); h1.y = __float2bfloat16(a.w);
    l0.x = __float2bfloat16(a.x - __bfloat162float(h0.x));
    l0.y = __float2bfloat16(a.y - __bfloat162float(h0.y));
    l1.x = __float2bfloat16(a.z - __bfloat162float(h1.x));
    l1.y = __float2bfloat16(a.w - __bfloat162float(h1.y));
    reinterpret_cast<__nv_bfloat162*>(qe_h + row * DD)[2 * t] = h0;
    reinterpret_cast<__nv_bfloat162*>(qe_h + row * DD)[2 * t + 1] = h1;
    reinterpret_cast<__nv_bfloat162*>(qe_l + row * DD)[2 * t] = l0;
    reinterpret_cast<__nv_bfloat162*>(qe_l + row * DD)[2 * t + 1] = l1;

    float b0 = a.x * w2.x, b1 = a.y * w2.y, b2 = a.z * w2.z, b3 = a.w * w2.w;
    h0.x = __float2bfloat16(b0); h0.y = __float2bfloat16(b1);
    h1.x = __float2bfloat16(b2); h1.y = __float2bfloat16(b3);
    l0.x = __float2bfloat16(b0 - __bfloat162float(h0.x));
    l0.y = __float2bfloat16(b1 - __bfloat162float(h0.y));
    l1.x = __float2bfloat16(b2 - __bfloat162float(h1.x));
    l1.y = __float2bfloat16(b3 - __bfloat162float(h1.y));
    reinterpret_cast<__nv_bfloat162*>(qe2_h + row * DD)[2 * t] = h0;
    reinterpret_cast<__nv_bfloat162*>(qe2_h + row * DD)[2 * t + 1] = h1;
    reinterpret_cast<__nv_bfloat162*>(qe2_l + row * DD)[2 * t] = l0;
    reinterpret_cast<__nv_bfloat162*>(qe2_l + row * DD)[2 * t + 1] = l1;

    float p = a.x * vv.x + a.y * vv.y + a.z * vv.z + a.w * vv.w;
    float q = a.x * w1.x + a.y * w1.y + a.z * w1.z + a.w * w1.w;
    __shared__ float red[16];
    #pragma unroll
    for (int o = 16; o; o >>= 1) {
        p += __shfl_xor_sync(0xffffffffu, p, o);
        q += __shfl_xor_sync(0xffffffffu, q, o);
    }
    if ((t & 31) == 0) { red[t >> 5] = p; red[8 + (t >> 5)] = q; }
    __syncthreads();
    if (t == 0) {
        float s = 0.f, s2 = 0.f;
        #pragma unroll
        for (int i = 0; i < 8; i++) { s += red[i]; s2 += red[8 + i]; }
        qv[row] = s;
        y1[row] = s2;
    }
}

// ---------------------------------------------------------------------------
// v[d] = sum_h Wq[d,h] * br[h]
// ---------------------------------------------------------------------------
__global__ void __launch_bounds__(256) matvec_k(
    const float* __restrict__ W, const float* __restrict__ b,
    float* __restrict__ v, int H)
{
    const float* row = W + (size_t)blockIdx.x * H;
    int t = threadIdx.x;
    float p = 0.f;
    for (int h = t * 4; h < H; h += 1024) {
        float4 wv = *reinterpret_cast<const float4*>(row + h);
        float4 bv = *reinterpret_cast<const float4*>(b + h);
        p = fmaf(wv.x, bv.x, p); p = fmaf(wv.y, bv.y, p);
        p = fmaf(wv.z, bv.z, p); p = fmaf(wv.w, bv.w, p);
    }
    __shared__ float red[8];
    #pragma unroll
    for (int o = 16; o; o >>= 1) p += __shfl_xor_sync(0xffffffffu, p, o);
    if ((t & 31) == 0) red[t >> 5] = p;
    __syncthreads();
    if (t == 0) {
        float s = 0.f;
        #pragma unroll
        for (int i = 0; i < 8; i++) s += red[i];
        v[blockIdx.x] = s;
    }
}

// ---------------------------------------------------------------------------
extern "C" void kernel_launch(void* const* d_in, const int* in_sizes, int n_in,
                              void* d_out, int out_size)
{
    const float* region = (const float*)d_in[0];
    const float* query  = (const float*)d_in[1];
    const float* Wr     = (const float*)d_in[2];
    const float* br     = (const float*)d_in[3];
    const float* Wq     = (const float*)d_in[4];
    const float* bq     = (const float*)d_in[5];
    const float* Ws     = (const float*)d_in[6];
    const float* bs     = (const float*)d_in[7];
    float* out = (float*)d_out;
    (void)bq;  // softmax-invariant terms drop out

    __nv_bfloat16 *Wr_h, *Wr_l, *Wq_h, *Wq_l, *M2_h, *M2_l;
    __nv_bfloat16 *rf_h, *rf_l, *qe_h, *qe_l, *qe2_h, *qe2_l, *Nt_h, *Nt_l;
    float4 *partb;
    float *v, *qv, *y1, *rd0;
    cudaGetSymbolAddress((void**)&Wr_h, g_Wr_h);
    cudaGetSymbolAddress((void**)&Wr_l, g_Wr_l);
    cudaGetSymbolAddress((void**)&Wq_h, g_Wq_h);
    cudaGetSymbolAddress((void**)&Wq_l, g_Wq_l);
    cudaGetSymbolAddress((void**)&M2_h, g_M2_h);
    cudaGetSymbolAddress((void**)&M2_l, g_M2_l);
    cudaGetSymbolAddress((void**)&rf_h, g_rf_h);
    cudaGetSymbolAddress((void**)&rf_l, g_rf_l);
    cudaGetSymbolAddress((void**)&qe_h, g_qe_h);
    cudaGetSymbolAddress((void**)&qe_l, g_qe_l);
    cudaGetSymbolAddress((void**)&qe2_h, g_qe2_h);
    cudaGetSymbolAddress((void**)&qe2_l, g_qe2_l);
    cudaGetSymbolAddress((void**)&Nt_h, g_Nt_h);
    cudaGetSymbolAddress((void**)&Nt_l, g_Nt_l);
    cudaGetSymbolAddress((void**)&partb, g_part);
    cudaGetSymbolAddress((void**)&v, g_v);
    cudaGetSymbolAddress((void**)&qv, g_qv);
    cudaGetSymbolAddress((void**)&y1, g_y1);
    cudaGetSymbolAddress((void**)&rd0, g_rd0);

    const int SMEM1 = 3 * (2 * 8192 + 2 * 16384);       // 147456 (3-stage, 48KB)
    const int SMEMD = 4 * (2 * 8192 + 4 * 8192);        // 196608 (4-stage, 48KB)
    cudaFuncSetAttribute(gemm_mma1, cudaFuncAttributeMaxDynamicSharedMemorySize, SMEM1);
    cudaFuncSetAttribute(gemm_dual, cudaFuncAttributeMaxDynamicSharedMemorySize, SMEMD);

    // 1) weight splits + bias matvec
    split2_k<<<512, 256>>>((const float4*)Wr, Wr_h, Wr_l, DD * HH / 4);
    split2_k<<<512, 256>>>((const float4*)Wq, Wq_h, Wq_l, DD * HH / 4);
    matvec_k<<<DD, 256>>>(Wq, br, v, HH);
    // 2) fused activation prep (single pass over region and query)
    region_prep_k<<<BB * RR, 256>>>(region, Ws, rf_h, rf_l, rd0);
    query_prep_k<<<BB * TT, 256>>>(query, v, Ws + DD, Ws + 2 * DD,
                                   qe_h, qe_l, qe2_h, qe2_l, qv, y1);
    // 3) M2[d,e] = sum_h Wr[d,h] Wq[e,h]  (e contiguous), split output
    gemm_mma1<<<dim3(DD / 128, DD / 64, 1), 256, SMEM1>>>(
        Wr_h, Wr_l, Wq_h, Wq_l, M2_h, M2_l, HH, 0, 0, 0, DD);
    // 4) Nt[b][t,d] = sum_e qe[b,t,e] M2[d,e]  (d contiguous), split output
    gemm_mma1<<<dim3(DD / 128, TT / 64, BB), 256, SMEM1>>>(
        qe_h, qe_l, M2_h, M2_l, Nt_h, Nt_l,
        DD, (size_t)TT * DD, 0, (size_t)TT * DD, DD);
    // 5) dual GEMM (64x64 tiles, 4-stage) with fused split-softmax -> partials
    gemm_dual<<<dim3(TT / 64, RR / 64, BB), 256, SMEMD>>>(
        rf_h, rf_l, Nt_h, Nt_l, qe2_h, qe2_l, qv, y1, partb,
        DD, (size_t)RR * DD, (size_t)TT * DD);
    // 6) finalize: merge 8 partials -> out
    finalize_k<<<BB * RR / 256, 256>>>(partb, rd0, bs, out);
}

// round 14
// speedup vs baseline: 1.0648x; 1.0648x over previous
#include <cuda_runtime.h>
#include <cuda_bf16.h>

#define BB 16
#define RR 1024
#define TT 512
#define DD 1024
#define HH 1024

// ---------------------------------------------------------------------------
// Scratch (device globals — allocations are forbidden)
// ---------------------------------------------------------------------------
__device__ __nv_bfloat16 g_Wr_h[DD * HH], g_Wr_l[DD * HH];
__device__ __nv_bfloat16 g_Wq_h[DD * HH], g_Wq_l[DD * HH];
__device__ __nv_bfloat16 g_M2_h[DD * DD], g_M2_l[DD * DD];       // M2[d,e] = sum_h Wr[d,h]Wq[e,h]
__device__ __nv_bfloat16 g_rf_h[(size_t)BB * RR * DD], g_rf_l[(size_t)BB * RR * DD];
__device__ __nv_bfloat16 g_qe_h[(size_t)BB * TT * DD], g_qe_l[(size_t)BB * TT * DD];
__device__ __nv_bfloat16 g_qe2_h[(size_t)BB * TT * DD], g_qe2_l[(size_t)BB * TT * DD]; // qe*Ws2
__device__ __nv_bfloat16 g_Nt_h[(size_t)BB * TT * DD], g_Nt_l[(size_t)BB * TT * DD];   // Nt[b][t,d]
__device__ float4        g_part[(size_t)BB * RR * 4];   // (m, den, num, pad) per t-slice
__device__ float         g_v[DD];
__device__ float         g_qv[BB * TT];
__device__ float         g_y1[BB * TT];
__device__ float         g_rd0[BB * RR];

// ---------------------------------------------------------------------------
// PTX helpers (sm_80-level features only: ldmatrix, cp.async, mma.sync)
// ---------------------------------------------------------------------------
__device__ __forceinline__ unsigned smem_u32(const void* p) {
    unsigned a;
    asm("{ .reg .u64 t; cvta.to.shared.u64 t, %1; cvt.u32.u64 %0, t; }" : "=r"(a) : "l"(p));
    return a;
}

#define CP_ASYNC16(dst, src) \
    asm volatile("cp.async.cg.shared.global [%0], [%1], 16;" :: "r"(dst), "l"(src))
#define CP_COMMIT() asm volatile("cp.async.commit_group;" ::: "memory")
#define CP_WAIT0()  asm volatile("cp.async.wait_group 0;" ::: "memory")
#define CP_WAIT1()  asm volatile("cp.async.wait_group 1;" ::: "memory")

__device__ __forceinline__ void ldsm4(unsigned* r, unsigned addr) {
    asm volatile("ldmatrix.sync.aligned.m8n8.x4.shared.b16 {%0,%1,%2,%3}, [%4];"
                 : "=r"(r[0]), "=r"(r[1]), "=r"(r[2]), "=r"(r[3]) : "r"(addr));
}

__device__ __forceinline__ void mma_bf16(float* c, const unsigned* a, const unsigned* b) {
    asm volatile(
        "mma.sync.aligned.m16n8k16.row.col.f32.bf16.bf16.f32 "
        "{%0,%1,%2,%3}, {%4,%5,%6,%7}, {%8,%9}, {%0,%1,%2,%3};"
        : "+f"(c[0]), "+f"(c[1]), "+f"(c[2]), "+f"(c[3])
        : "r"(a[0]), "r"(a[1]), "r"(a[2]), "r"(a[3]), "r"(b[0]), "r"(b[1]));
}

__device__ __forceinline__ unsigned swz(unsigned off) {
    return off ^ ((off >> 3) & 0x70);
}

// ---------------------------------------------------------------------------
// Split-bf16 GEMM, CTA tile 64x128 (8 warps = 2M x 4N, warp tile 32x32).
// 3 terms: hh + hl + lh. K chunks of 64 bf16 (SW128), 3-stage cp.async.
// Split hi/lo bf16 output. Used for M2 and Nt.
// ---------------------------------------------------------------------------
__global__ void __launch_bounds__(256) gemm_mma1(
    const __nv_bfloat16* __restrict__ A0, const __nv_bfloat16* __restrict__ A1,
    const __nv_bfloat16* __restrict__ B0, const __nv_bfloat16* __restrict__ B1,
    __nv_bfloat16* __restrict__ Ch, __nv_bfloat16* __restrict__ Cl,
    int K, size_t sA, size_t sB, size_t sC, int ldc)
{
    constexpr unsigned TA = 64 * 128;     // 8 KB per A split tile
    constexpr unsigned TB = 128 * 128;    // 16 KB per B split tile
    constexpr unsigned STAGE = 2 * TA + 2 * TB;   // 48 KB

    extern __shared__ char smem[];
    const unsigned sbase = smem_u32(smem);

    const int tid = threadIdx.x;
    const int lid = tid & 31;
    const int wid = tid >> 5;
    const int wm = wid & 1;
    const int wn = wid >> 1;

    const size_t zb = blockIdx.z;
    const __nv_bfloat16* AP[2] = { A0 + zb * sA, A1 + zb * sA };
    const __nv_bfloat16* BP[2] = { B0 + zb * sB, B1 + zb * sB };
    const size_t rm0 = (size_t)blockIdx.y * 64;
    const size_t rn0 = (size_t)blockIdx.x * 128;
    const int NC = K >> 6;

    float c[2][4][4] = {};

    const int al_r  = lid & 15;
    const int al_k  = (lid >> 4) & 1;
    const int bl_r  = (lid & 7) + ((lid >> 4) << 3);
    const int bl_k  = (lid >> 3) & 1;

    auto load_stage = [&](int st, int ck) {
        const unsigned sdst = sbase + (unsigned)st * STAGE;
        const int k0 = ck << 6;
        #pragma unroll
        for (int sp = 0; sp < 2; sp++) {
            #pragma unroll
            for (int i = 0; i < 2; i++) {
                int idx = i * 256 + tid;
                int row = idx >> 3, g = idx & 7;
                const __nv_bfloat16* gs = AP[sp] + (rm0 + row) * (size_t)K + k0 + g * 8;
                unsigned d = sdst + (unsigned)sp * TA + swz((unsigned)(row * 128 + g * 16));
                CP_ASYNC16(d, gs);
            }
        }
        #pragma unroll
        for (int sp = 0; sp < 2; sp++) {
            #pragma unroll
            for (int i = 0; i < 4; i++) {
                int idx = i * 256 + tid;
                int row = idx >> 3, g = idx & 7;
                const __nv_bfloat16* gs = BP[sp] + (rn0 + row) * (size_t)K + k0 + g * 8;
                unsigned d = sdst + 2 * TA + (unsigned)sp * TB +
                             swz((unsigned)(row * 128 + g * 16));
                CP_ASYNC16(d, gs);
            }
        }
    };

    load_stage(0, 0); CP_COMMIT();
    load_stage(1, 1); CP_COMMIT();

    for (int ck = 0; ck < NC; ck++) {
        if (ck + 1 < NC) CP_WAIT1(); else CP_WAIT0();
        __syncthreads();
        if (ck + 2 < NC) {
            load_stage((ck + 2) % 3, ck + 2);
            CP_COMMIT();
        }

        const unsigned sb2 = sbase + (unsigned)(ck % 3) * STAGE;
        #pragma unroll
        for (int ks = 0; ks < 4; ks++) {
            unsigned af[2][2][4];
            unsigned bf[2][4][2];
            #pragma unroll
            for (int sp = 0; sp < 2; sp++) {
                #pragma unroll
                for (int mt = 0; mt < 2; mt++) {
                    unsigned addr = sb2 + (unsigned)sp * TA +
                        swz((unsigned)((wm * 32 + mt * 16 + al_r) * 128 + ks * 32 + al_k * 16));
                    ldsm4(af[sp][mt], addr);
                }
                #pragma unroll
                for (int np = 0; np < 2; np++) {
                    unsigned r[4];
                    unsigned addr = sb2 + 2 * TA + (unsigned)sp * TB +
                        swz((unsigned)((wn * 32 + np * 16 + bl_r) * 128 + ks * 32 + bl_k * 16));
                    ldsm4(r, addr);
                    bf[sp][2 * np][0] = r[0]; bf[sp][2 * np][1] = r[1];
                    bf[sp][2 * np + 1][0] = r[2]; bf[sp][2 * np + 1][1] = r[3];
                }
            }
            #pragma unroll
            for (int tm = 0; tm < 3; tm++) {
                const int i = (tm == 2) ? 1 : 0;
                const int j = (tm == 1) ? 1 : 0;
                #pragma unroll
                for (int mt = 0; mt < 2; mt++)
                    #pragma unroll
                    for (int nt = 0; nt < 4; nt++)
                        mma_bf16(c[mt][nt], af[i][mt], bf[j][nt]);
            }
        }
    }
    __syncthreads();

    const int qr = lid >> 2;
    const int qc = (lid & 3) * 2;
    #pragma unroll
    for (int mt = 0; mt < 2; mt++) {
        #pragma unroll
        for (int nt = 0; nt < 4; nt++) {
            size_t gr = rm0 + wm * 32 + mt * 16 + qr;
            int gc = (int)rn0 + wn * 32 + nt * 8 + qc;
            #pragma unroll
            for (int half = 0; half < 2; half++) {
                float v0 = c[mt][nt][2 * half + 0];
                float v1 = c[mt][nt][2 * half + 1];
                size_t o = zb * sC + (gr + half * 8) * (size_t)ldc + gc;
                __nv_bfloat162 hv, lv;
                hv.x = __float2bfloat16(v0);
                hv.y = __float2bfloat16(v1);
                lv.x = __float2bfloat16(v0 - __bfloat162float(hv.x));
                lv.y = __float2bfloat16(v1 - __bfloat162float(hv.y));
                *reinterpret_cast<__nv_bfloat162*>(Ch + o) = hv;
                *reinterpret_cast<__nv_bfloat162*>(Cl + o) = lv;
            }
        }
    }
}

// ---------------------------------------------------------------------------
// Dual-B GEMM with fused split-softmax epilogue. CTA tile 64x128, 2-stage
// (80 KB/stage). c1 = rf@Nt^T, c2 = rf@qe2^T. Per row: partial softmax over
// this CTA's 128 t-values -> one float4 (m, den, num, 0) per (row, t-slice).
// ---------------------------------------------------------------------------
__global__ void __launch_bounds__(256) gemm_dual(
    const __nv_bfloat16* __restrict__ A0, const __nv_bfloat16* __restrict__ A1,
    const __nv_bfloat16* __restrict__ B0, const __nv_bfloat16* __restrict__ B1,
    const __nv_bfloat16* __restrict__ C0, const __nv_bfloat16* __restrict__ C1,
    const float* __restrict__ qv, const float* __restrict__ y1,
    float4* __restrict__ part,
    int K, size_t sA, size_t sB)
{
    constexpr unsigned TA = 64 * 128;     // 8 KB
    constexpr unsigned TB = 128 * 128;    // 16 KB
    constexpr unsigned STAGE = 2 * TA + 4 * TB;   // 80 KB

    extern __shared__ char smem[];
    const unsigned sbase = smem_u32(smem);

    const int tid = threadIdx.x;
    const int lid = tid & 31;
    const int wid = tid >> 5;
    const int wm = wid & 1;
    const int wn = wid >> 1;

    const size_t zb = blockIdx.z;
    const __nv_bfloat16* AP[2] = { A0 + zb * sA, A1 + zb * sA };
    const __nv_bfloat16* BP[4] = { B0 + zb * sB, B1 + zb * sB,
                                   C0 + zb * sB, C1 + zb * sB };
    const size_t rm0 = (size_t)blockIdx.y * 64;
    const size_t rn0 = (size_t)blockIdx.x * 128;
    const int NC = K >> 6;

    float c1[2][4][4] = {};
    float c2[2][4][4] = {};

    const int al_r  = lid & 15;
    const int al_k  = (lid >> 4) & 1;
    const int bl_r  = (lid & 7) + ((lid >> 4) << 3);
    const int bl_k  = (lid >> 3) & 1;

    auto load_stage = [&](int st, int ck) {
        const unsigned sdst = sbase + (unsigned)st * STAGE;
        const int k0 = ck << 6;
        #pragma unroll
        for (int sp = 0; sp < 2; sp++) {
            #pragma unroll
            for (int i = 0; i < 2; i++) {
                int idx = i * 256 + tid;
                int row = idx >> 3, g = idx & 7;
                const __nv_bfloat16* gs = AP[sp] + (rm0 + row) * (size_t)K + k0 + g * 8;
                unsigned d = sdst + (unsigned)sp * TA + swz((unsigned)(row * 128 + g * 16));
                CP_ASYNC16(d, gs);
            }
        }
        #pragma unroll
        for (int t4 = 0; t4 < 4; t4++) {
            #pragma unroll
            for (int i = 0; i < 4; i++) {
                int idx = i * 256 + tid;
                int row = idx >> 3, g = idx & 7;
                const __nv_bfloat16* gs = BP[t4] + (rn0 + row) * (size_t)K + k0 + g * 8;
                unsigned d = sdst + 2 * TA + (unsigned)t4 * TB +
                             swz((unsigned)(row * 128 + g * 16));
                CP_ASYNC16(d, gs);
            }
        }
    };

    load_stage(0, 0); CP_COMMIT();

    for (int ck = 0; ck < NC; ck++) {
        if (ck + 1 < NC) {
            load_stage((ck + 1) & 1, ck + 1);
            CP_COMMIT();
            CP_WAIT1();
        } else {
            CP_WAIT0();
        }
        __syncthreads();

        const unsigned sb2 = sbase + (unsigned)(ck & 1) * STAGE;
        #pragma unroll
        for (int ks = 0; ks < 4; ks++) {
            unsigned af[2][2][4];
            #pragma unroll
            for (int sp = 0; sp < 2; sp++)
                #pragma unroll
                for (int mt = 0; mt < 2; mt++) {
                    unsigned addr = sb2 + (unsigned)sp * TA +
                        swz((unsigned)((wm * 32 + mt * 16 + al_r) * 128 + ks * 32 + al_k * 16));
                    ldsm4(af[sp][mt], addr);
                }
            {
                unsigned bf[2][4][2];
                #pragma unroll
                for (int sp = 0; sp < 2; sp++)
                    #pragma unroll
                    for (int np = 0; np < 2; np++) {
                        unsigned r[4];
                        unsigned addr = sb2 + 2 * TA + (unsigned)sp * TB +
                            swz((unsigned)((wn * 32 + np * 16 + bl_r) * 128 + ks * 32 + bl_k * 16));
                        ldsm4(r, addr);
                        bf[sp][2 * np][0] = r[0]; bf[sp][2 * np][1] = r[1];
                        bf[sp][2 * np + 1][0] = r[2]; bf[sp][2 * np + 1][1] = r[3];
                    }
                #pragma unroll
                for (int tm = 0; tm < 3; tm++) {
                    const int i = (tm == 2) ? 1 : 0;
                    const int j = (tm == 1) ? 1 : 0;
                    #pragma unroll
                    for (int mt = 0; mt < 2; mt++)
                        #pragma unroll
                        for (int nt = 0; nt < 4; nt++)
                            mma_bf16(c1[mt][nt], af[i][mt], bf[j][nt]);
                }
            }
            {
                unsigned bf[2][4][2];
                #pragma unroll
                for (int sp = 0; sp < 2; sp++)
                    #pragma unroll
                    for (int np = 0; np < 2; np++) {
                        unsigned r[4];
                        unsigned addr = sb2 + 2 * TA + (unsigned)(2 + sp) * TB +
                            swz((unsigned)((wn * 32 + np * 16 + bl_r) * 128 + ks * 32 + bl_k * 16));
                        ldsm4(r, addr);
                        bf[sp][2 * np][0] = r[0]; bf[sp][2 * np][1] = r[1];
                        bf[sp][2 * np + 1][0] = r[2]; bf[sp][2 * np + 1][1] = r[3];
                    }
                #pragma unroll
                for (int tm = 0; tm < 3; tm++) {
                    const int i = (tm == 2) ? 1 : 0;
                    const int j = (tm == 1) ? 1 : 0;
                    #pragma unroll
                    for (int mt = 0; mt < 2; mt++)
                        #pragma unroll
                        for (int nt = 0; nt < 4; nt++)
                            mma_bf16(c2[mt][nt], af[i][mt], bf[j][nt]);
                }
            }
        }
        __syncthreads();
    }

    // ---- Fused split-softmax epilogue ----
    const int qr = lid >> 2;
    const int qc = (lid & 3) * 2;
    const size_t boff = zb * TT;
    const int tbase = (int)rn0 + wn * 32;

    float2 qvv[4], y1v[4];
    #pragma unroll
    for (int nt = 0; nt < 4; nt++) {
        int t0 = tbase + nt * 8 + qc;
        qvv[nt] = *reinterpret_cast<const float2*>(qv + boff + t0);
        y1v[nt] = *reinterpret_cast<const float2*>(y1 + boff + t0);
    }

    float* sp = reinterpret_cast<float*>(smem);   // [64 rows][4 wn][3] = 3 KB

    #pragma unroll
    for (int mt = 0; mt < 2; mt++) {
        #pragma unroll
        for (int half = 0; half < 2; half++) {
            float sv[8];
            float m = -1e30f;
            #pragma unroll
            for (int nt = 0; nt < 4; nt++) {
                sv[2 * nt]     = c1[mt][nt][2 * half]     + qvv[nt].x;
                sv[2 * nt + 1] = c1[mt][nt][2 * half + 1] + qvv[nt].y;
                m = fmaxf(m, fmaxf(sv[2 * nt], sv[2 * nt + 1]));
            }
            float den = 0.f, num = 0.f;
            #pragma unroll
            for (int nt = 0; nt < 4; nt++) {
                float e0 = __expf(sv[2 * nt] - m);
                float e1 = __expf(sv[2 * nt + 1] - m);
                den += e0 + e1;
                num = fmaf(e0, y1v[nt].x + c2[mt][nt][2 * half], num);
                num = fmaf(e1, y1v[nt].y + c2[mt][nt][2 * half + 1], num);
            }
            // merge across the 4 qc-lanes (lid^1, lid^2)
            #pragma unroll
            for (int o = 1; o <= 2; o <<= 1) {
                float mo = __shfl_xor_sync(0xffffffffu, m, o);
                float dn = __shfl_xor_sync(0xffffffffu, den, o);
                float no = __shfl_xor_sync(0xffffffffu, num, o);
                float mn = fmaxf(m, mo);
                float sa = __expf(m - mn), sb = __expf(mo - mn);
                den = den * sa + dn * sb;
                num = num * sa + no * sb;
                m = mn;
            }
            if ((lid & 3) == 0) {
                int lr = wm * 32 + mt * 16 + qr + half * 8;
                sp[(lr * 4 + wn) * 3 + 0] = m;
                sp[(lr * 4 + wn) * 3 + 1] = den;
                sp[(lr * 4 + wn) * 3 + 2] = num;
            }
        }
    }
    __syncthreads();
    if (tid < 64) {
        float m = -1e30f;
        #pragma unroll
        for (int w = 0; w < 4; w++) m = fmaxf(m, sp[(tid * 4 + w) * 3]);
        float den = 0.f, num = 0.f;
        #pragma unroll
        for (int w = 0; w < 4; w++) {
            float s = __expf(sp[(tid * 4 + w) * 3] - m);
            den = fmaf(sp[(tid * 4 + w) * 3 + 1], s, den);
            num = fmaf(sp[(tid * 4 + w) * 3 + 2], s, num);
        }
        size_t row = zb * RR + rm0 + tid;
        part[row * 4 + blockIdx.x] = make_float4(m, den, num, 0.f);
    }
}

// ---------------------------------------------------------------------------
// Finalize: merge 4 softmax partials per row; out = rd0 + num/den + bs
// ---------------------------------------------------------------------------
__global__ void __launch_bounds__(256) finalize_k(
    const float4* __restrict__ part, const float* __restrict__ rd0,
    const float* __restrict__ bs, float* __restrict__ out)
{
    int i = blockIdx.x * 256 + threadIdx.x;
    float4 p0 = part[(size_t)i * 4 + 0];
    float4 p1 = part[(size_t)i * 4 + 1];
    float4 p2 = part[(size_t)i * 4 + 2];
    float4 p3 = part[(size_t)i * 4 + 3];
    float m = fmaxf(fmaxf(p0.x, p1.x), fmaxf(p2.x, p3.x));
    float s0 = __expf(p0.x - m), s1 = __expf(p1.x - m);
    float s2 = __expf(p2.x - m), s3 = __expf(p3.x - m);
    float den = p0.y * s0 + p1.y * s1 + p2.y * s2 + p3.y * s3;
    float num = p0.z * s0 + p1.z * s1 + p2.z * s2 + p3.z * s3;
    out[i] = rd0[i] + num / den + bs[0];
}

// ---------------------------------------------------------------------------
// Merged weight split: blocks [0,512) handle Wr, [512,1024) handle Wq.
// ---------------------------------------------------------------------------
__global__ void __launch_bounds__(256) split2w_k(
    const float4* __restrict__ Wr, const float4* __restrict__ Wq,
    __nv_bfloat16* __restrict__ Wr_h, __nv_bfloat16* __restrict__ Wr_l,
    __nv_bfloat16* __restrict__ Wq_h, __nv_bfloat16* __restrict__ Wq_l)
{
    const int n4 = DD * HH / 4;
    const bool second = blockIdx.x >= 512;
    const float4* x = second ? Wq : Wr;
    __nv_bfloat16* h = second ? Wq_h : Wr_h;
    __nv_bfloat16* l = second ? Wq_l : Wr_l;
    int b0 = second ? (blockIdx.x - 512) : blockIdx.x;
    for (int i = b0 * 256 + threadIdx.x; i < n4; i += 512 * 256) {
        float4 v = x[i];
        float a[4] = {v.x, v.y, v.z, v.w};
        __nv_bfloat16 hh[4], ll[4];
        #pragma unroll
        for (int k = 0; k < 4; k++) {
            hh[k] = __float2bfloat16(a[k]);
            ll[k] = __float2bfloat16(a[k] - __bfloat162float(hh[k]));
        }
        __nv_bfloat162 p0, p1;
        p0.x = hh[0]; p0.y = hh[1]; p1.x = hh[2]; p1.y = hh[3];
        reinterpret_cast<__nv_bfloat162*>(h)[2 * i] = p0;
        reinterpret_cast<__nv_bfloat162*>(h)[2 * i + 1] = p1;
        p0.x = ll[0]; p0.y = ll[1]; p1.x = ll[2]; p1.y = ll[3];
        reinterpret_cast<__nv_bfloat162*>(l)[2 * i] = p0;
        reinterpret_cast<__nv_bfloat162*>(l)[2 * i + 1] = p1;
    }
}

// ---------------------------------------------------------------------------
// region prep: one CTA per (b,r) row. Writes rf_h/rf_l; computes rd0 = row.Ws0.
// ---------------------------------------------------------------------------
__global__ void __launch_bounds__(256) region_prep_k(
    const float* __restrict__ region, const float* __restrict__ Ws0,
    __nv_bfloat16* __restrict__ rf_h, __nv_bfloat16* __restrict__ rf_l,
    float* __restrict__ rd0)
{
    size_t row = blockIdx.x;
    int t = threadIdx.x;
    float4 a = *reinterpret_cast<const float4*>(region + row * DD + t * 4);
    float4 w = *reinterpret_cast<const float4*>(Ws0 + t * 4);

    __nv_bfloat162 h0, h1, l0, l1;
    h0.x = __float2bfloat16(a.x); h0.y = __float2bfloat16(a.y);
    h1.x = __float2bfloat16(a.z); h1.y = __float2bfloat16(a.w);
    l0.x = __float2bfloat16(a.x - __bfloat162float(h0.x));
    l0.y = __float2bfloat16(a.y - __bfloat162float(h0.y));
    l1.x = __float2bfloat16(a.z - __bfloat162float(h1.x));
    l1.y = __float2bfloat16(a.w - __bfloat162float(h1.y));
    reinterpret_cast<__nv_bfloat162*>(rf_h + row * DD)[2 * t] = h0;
    reinterpret_cast<__nv_bfloat162*>(rf_h + row * DD)[2 * t + 1] = h1;
    reinterpret_cast<__nv_bfloat162*>(rf_l + row * DD)[2 * t] = l0;
    reinterpret_cast<__nv_bfloat162*>(rf_l + row * DD)[2 * t + 1] = l1;

    float p = a.x * w.x + a.y * w.y + a.z * w.z + a.w * w.w;
    __shared__ float red[8];
    #pragma unroll
    for (int o = 16; o; o >>= 1) p += __shfl_xor_sync(0xffffffffu, p, o);
    if ((t & 31) == 0) red[t >> 5] = p;
    __syncthreads();
    if (t == 0) {
        float s = 0.f;
        #pragma unroll
        for (int i = 0; i < 8; i++) s += red[i];
        rd0[row] = s;
    }
}

// ---------------------------------------------------------------------------
// query prep: one CTA per (b,t) row. Writes qe_h/l and qe2_h/l (= qe*Ws2);
// computes qv = row.v and y1 = row.Ws1.
// ---------------------------------------------------------------------------
__global__ void __launch_bounds__(256) query_prep_k(
    const float* __restrict__ query, const float* __restrict__ v,
    const float* __restrict__ Ws1, const float* __restrict__ Ws2,
    __nv_bfloat16* __restrict__ qe_h, __nv_bfloat16* __restrict__ qe_l,
    __nv_bfloat16* __restrict__ qe2_h, __nv_bfloat16* __restrict__ qe2_l,
    float* __restrict__ qv, float* __restrict__ y1)
{
    size_t row = blockIdx.x;
    int t = threadIdx.x;
    float4 a = *reinterpret_cast<const float4*>(query + row * DD + t * 4);
    float4 vv = *reinterpret_cast<const float4*>(v + t * 4);
    float4 w1 = *reinterpret_cast<const float4*>(Ws1 + t * 4);
    float4 w2 = *reinterpret_cast<const float4*>(Ws2 + t * 4);

    __nv_bfloat162 h0, h1, l0, l1;
    h0.x = __float2bfloat16(a.x); h0.y = __float2bfloat16(a.y);
    h1.x = __float2bfloat16(a.z); h1.y = __float2bfloat16(a.w);
    l0.x = __float2bfloat16(a.x - __bfloat162float(h0.x));
    l0.y = __float2bfloat16(a.y - __bfloat162float(h0.y));
    l1.x = __float2bfloat16(a.z - __bfloat162float(h1.x));
    l1.y = __float2bfloat16(a.w - __bfloat162float(h1.y));
    reinterpret_cast<__nv_bfloat162*>(qe_h + row * DD)[2 * t] = h0;
    reinterpret_cast<__nv_bfloat162*>(qe_h + row * DD)[2 * t + 1] = h1;
    reinterpret_cast<__nv_bfloat162*>(qe_l + row * DD)[2 * t] = l0;
    reinterpret_cast<__nv_bfloat162*>(qe_l + row * DD)[2 * t + 1] = l1;

    float b0 = a.x * w2.x, b1 = a.y * w2.y, b2 = a.z * w2.z, b3 = a.w * w2.w;
    h0.x = __float2bfloat16(b0); h0.y = __float2bfloat16(b1);
    h1.x = __float2bfloat16(b2); h1.y = __float2bfloat16(b3);
    l0.x = __float2bfloat16(b0 - __bfloat162float(h0.x));
    l0.y = __float2bfloat16(b1 - __bfloat162float(h0.y));
    l1.x = __float2bfloat16(b2 - __bfloat162float(h1.x));
    l1.y = __float2bfloat16(b3 - __bfloat162float(h1.y));
    reinterpret_cast<__nv_bfloat162*>(qe2_h + row * DD)[2 * t] = h0;
    reinterpret_cast<__nv_bfloat162*>(qe2_h + row * DD)[2 * t + 1] = h1;
    reinterpret_cast<__nv_bfloat162*>(qe2_l + row * DD)[2 * t] = l0;
    reinterpret_cast<__nv_bfloat162*>(qe2_l + row * DD)[2 * t + 1] = l1;

    float p = a.x * vv.x + a.y * vv.y + a.z * vv.z + a.w * vv.w;
    float q = a.x * w1.x + a.y * w1.y + a.z * w1.z + a.w * w1.w;
    __shared__ float red[16];
    #pragma unroll
    for (int o = 16; o; o >>= 1) {
        p += __shfl_xor_sync(0xffffffffu, p, o);
        q += __shfl_xor_sync(0xffffffffu, q, o);
    }
    if ((t & 31) == 0) { red[t >> 5] = p; red[8 + (t >> 5)] = q; }
    __syncthreads();
    if (t == 0) {
        float s = 0.f, s2 = 0.f;
        #pragma unroll
        for (int i = 0; i < 8; i++) { s += red[i]; s2 += red[8 + i]; }
        qv[row] = s;
        y1[row] = s2;
    }
}

// ---------------------------------------------------------------------------
// v[d] = sum_h Wq[d,h] * br[h]
// ---------------------------------------------------------------------------
__global__ void __launch_bounds__(256) matvec_k(
    const float* __restrict__ W, const float* __restrict__ b,
    float* __restrict__ v, int H)
{
    const float* row = W + (size_t)blockIdx.x * H;
    int t = threadIdx.x;
    float p = 0.f;
    for (int h = t * 4; h < H; h += 1024) {
        float4 wv = *reinterpret_cast<const float4*>(row + h);
        float4 bv = *reinterpret_cast<const float4*>(b + h);
        p = fmaf(wv.x, bv.x, p); p = fmaf(wv.y, bv.y, p);
        p = fmaf(wv.z, bv.z, p); p = fmaf(wv.w, bv.w, p);
    }
    __shared__ float red[8];
    #pragma unroll
    for (int o = 16; o; o >>= 1) p += __shfl_xor_sync(0xffffffffu, p, o);
    if ((t & 31) == 0) red[t >> 5] = p;
    __syncthreads();
    if (t == 0) {
        float s = 0.f;
        #pragma unroll
        for (int i = 0; i < 8; i++) s += red[i];
        v[blockIdx.x] = s;
    }
}

// ---------------------------------------------------------------------------
extern "C" void kernel_launch(void* const* d_in, const int* in_sizes, int n_in,
                              void* d_out, int out_size)
{
    const float* region = (const float*)d_in[0];
    const float* query  = (const float*)d_in[1];
    const float* Wr     = (const float*)d_in[2];
    const float* br     = (const float*)d_in[3];
    const float* Wq     = (const float*)d_in[4];
    const float* bq     = (const float*)d_in[5];
    const float* Ws     = (const float*)d_in[6];
    const float* bs     = (const float*)d_in[7];
    float* out = (float*)d_out;
    (void)bq;  // softmax-invariant terms drop out

    __nv_bfloat16 *Wr_h, *Wr_l, *Wq_h, *Wq_l, *M2_h, *M2_l;
    __nv_bfloat16 *rf_h, *rf_l, *qe_h, *qe_l, *qe2_h, *qe2_l, *Nt_h, *Nt_l;
    float4 *partb;
    float *v, *qv, *y1, *rd0;
    cudaGetSymbolAddress((void**)&Wr_h, g_Wr_h);
    cudaGetSymbolAddress((void**)&Wr_l, g_Wr_l);
    cudaGetSymbolAddress((void**)&Wq_h, g_Wq_h);
    cudaGetSymbolAddress((void**)&Wq_l, g_Wq_l);
    cudaGetSymbolAddress((void**)&M2_h, g_M2_h);
    cudaGetSymbolAddress((void**)&M2_l, g_M2_l);
    cudaGetSymbolAddress((void**)&rf_h, g_rf_h);
    cudaGetSymbolAddress((void**)&rf_l, g_rf_l);
    cudaGetSymbolAddress((void**)&qe_h, g_qe_h);
    cudaGetSymbolAddress((void**)&qe_l, g_qe_l);
    cudaGetSymbolAddress((void**)&qe2_h, g_qe2_h);
    cudaGetSymbolAddress((void**)&qe2_l, g_qe2_l);
    cudaGetSymbolAddress((void**)&Nt_h, g_Nt_h);
    cudaGetSymbolAddress((void**)&Nt_l, g_Nt_l);
    cudaGetSymbolAddress((void**)&partb, g_part);
    cudaGetSymbolAddress((void**)&v, g_v);
    cudaGetSymbolAddress((void**)&qv, g_qv);
    cudaGetSymbolAddress((void**)&y1, g_y1);
    cudaGetSymbolAddress((void**)&rd0, g_rd0);

    const int SMEM1 = 3 * (2 * 8192 + 2 * 16384);       // 147456 (3-stage, 48KB)
    const int SMEMD = 2 * (2 * 8192 + 4 * 16384);       // 163840 (2-stage, 80KB)
    cudaFuncSetAttribute(gemm_mma1, cudaFuncAttributeMaxDynamicSharedMemorySize, SMEM1);
    cudaFuncSetAttribute(gemm_dual, cudaFuncAttributeMaxDynamicSharedMemorySize, SMEMD);

    // 1) merged weight splits + bias matvec
    split2w_k<<<1024, 256>>>((const float4*)Wr, (const float4*)Wq,
                             Wr_h, Wr_l, Wq_h, Wq_l);
    matvec_k<<<DD, 256>>>(Wq, br, v, HH);
    // 2) fused activation prep (single pass over region and query)
    region_prep_k<<<BB * RR, 256>>>(region, Ws, rf_h, rf_l, rd0);
    query_prep_k<<<BB * TT, 256>>>(query, v, Ws + DD, Ws + 2 * DD,
                                   qe_h, qe_l, qe2_h, qe2_l, qv, y1);
    // 3) M2[d,e] = sum_h Wr[d,h] Wq[e,h]  (e contiguous), split output
    gemm_mma1<<<dim3(DD / 128, DD / 64, 1), 256, SMEM1>>>(
        Wr_h, Wr_l, Wq_h, Wq_l, M2_h, M2_l, HH, 0, 0, 0, DD);
    // 4) Nt[b][t,d] = sum_e qe[b,t,e] M2[d,e]  (d contiguous), split output
    gemm_mma1<<<dim3(DD / 128, TT / 64, BB), 256, SMEM1>>>(
        qe_h, qe_l, M2_h, M2_l, Nt_h, Nt_l,
        DD, (size_t)TT * DD, 0, (size_t)TT * DD, DD);
    // 5) dual GEMM with fused split-softmax epilogue -> partials
    gemm_dual<<<dim3(TT / 128, RR / 64, BB), 256, SMEMD>>>(
        rf_h, rf_l, Nt_h, Nt_l, qe2_h, qe2_l, qv, y1, partb,
        DD, (size_t)RR * DD, (size_t)TT * DD);
    // 6) finalize: merge partials -> out
    finalize_k<<<BB * RR / 256, 256>>>(partb, rd0, bs, out);
}

// round 15
// speedup vs baseline: 1.1402x; 1.0708x over previous
#include <cuda_runtime.h>
#include <cuda_bf16.h>

#define BB 16
#define RR 1024
#define TT 512
#define DD 1024
#define HH 1024

// ---------------------------------------------------------------------------
// Scratch (device globals — allocations are forbidden)
// ---------------------------------------------------------------------------
__device__ __nv_bfloat16 g_Wr_h[DD * HH], g_Wr_l[DD * HH];
__device__ __nv_bfloat16 g_Wq_h[DD * HH], g_Wq_l[DD * HH];
__device__ __nv_bfloat16 g_M2_h[DD * DD], g_M2_l[DD * DD];       // M2[d,e] = sum_h Wr[d,h]Wq[e,h]
__device__ __nv_bfloat16 g_rf_h[(size_t)BB * RR * DD], g_rf_l[(size_t)BB * RR * DD];
__device__ __nv_bfloat16 g_qe_h[(size_t)BB * TT * DD], g_qe_l[(size_t)BB * TT * DD];
__device__ __nv_bfloat16 g_qe2_h[(size_t)BB * TT * DD], g_qe2_l[(size_t)BB * TT * DD]; // qe*Ws2
__device__ __nv_bfloat16 g_Nt_h[(size_t)BB * TT * DD], g_Nt_l[(size_t)BB * TT * DD];   // Nt[b][t,d]
__device__ float4        g_part[(size_t)BB * RR * 4];   // (m, den, num, pad) per t-slice
__device__ float         g_v[DD];
__device__ float         g_qv[BB * TT];
__device__ float         g_y1[BB * TT];
__device__ float         g_rd0[BB * RR];

// ---------------------------------------------------------------------------
// PTX helpers (sm_80-level features only: ldmatrix, cp.async, mma.sync)
// ---------------------------------------------------------------------------
__device__ __forceinline__ unsigned smem_u32(const void* p) {
    unsigned a;
    asm("{ .reg .u64 t; cvta.to.shared.u64 t, %1; cvt.u32.u64 %0, t; }" : "=r"(a) : "l"(p));
    return a;
}

#define CP_ASYNC16(dst, src) \
    asm volatile("cp.async.cg.shared.global [%0], [%1], 16;" :: "r"(dst), "l"(src))
#define CP_COMMIT() asm volatile("cp.async.commit_group;" ::: "memory")
#define CP_WAIT0()  asm volatile("cp.async.wait_group 0;" ::: "memory")
#define CP_WAIT1()  asm volatile("cp.async.wait_group 1;" ::: "memory")

__device__ __forceinline__ void ldsm4(unsigned* r, unsigned addr) {
    asm volatile("ldmatrix.sync.aligned.m8n8.x4.shared.b16 {%0,%1,%2,%3}, [%4];"
                 : "=r"(r[0]), "=r"(r[1]), "=r"(r[2]), "=r"(r[3]) : "r"(addr));
}

__device__ __forceinline__ void mma_bf16(float* c, const unsigned* a, const unsigned* b) {
    asm volatile(
        "mma.sync.aligned.m16n8k16.row.col.f32.bf16.bf16.f32 "
        "{%0,%1,%2,%3}, {%4,%5,%6,%7}, {%8,%9}, {%0,%1,%2,%3};"
        : "+f"(c[0]), "+f"(c[1]), "+f"(c[2]), "+f"(c[3])
        : "r"(a[0]), "r"(a[1]), "r"(a[2]), "r"(a[3]), "r"(b[0]), "r"(b[1]));
}

__device__ __forceinline__ unsigned swz(unsigned off) {
    return off ^ ((off >> 3) & 0x70);
}

// ---------------------------------------------------------------------------
// Split-bf16 GEMM, CTA tile 64x128 (8 warps = 2M x 4N, warp tile 32x32).
// 3 terms: hh + hl + lh. K chunks of 64 bf16 (SW128), 2-stage cp.async,
// 2 CTAs/SM (cross-CTA latency hiding). Split hi/lo bf16 output (M2, Nt).
// ---------------------------------------------------------------------------
__global__ void __launch_bounds__(256, 2) gemm_mma1(
    const __nv_bfloat16* __restrict__ A0, const __nv_bfloat16* __restrict__ A1,
    const __nv_bfloat16* __restrict__ B0, const __nv_bfloat16* __restrict__ B1,
    __nv_bfloat16* __restrict__ Ch, __nv_bfloat16* __restrict__ Cl,
    int K, size_t sA, size_t sB, size_t sC, int ldc)
{
    constexpr unsigned TA = 64 * 128;     // 8 KB per A split tile
    constexpr unsigned TB = 128 * 128;    // 16 KB per B split tile
    constexpr unsigned STAGE = 2 * TA + 2 * TB;   // 48 KB

    extern __shared__ char smem[];
    const unsigned sbase = smem_u32(smem);

    const int tid = threadIdx.x;
    const int lid = tid & 31;
    const int wid = tid >> 5;
    const int wm = wid & 1;
    const int wn = wid >> 1;

    const size_t zb = blockIdx.z;
    const __nv_bfloat16* AP[2] = { A0 + zb * sA, A1 + zb * sA };
    const __nv_bfloat16* BP[2] = { B0 + zb * sB, B1 + zb * sB };
    const size_t rm0 = (size_t)blockIdx.y * 64;
    const size_t rn0 = (size_t)blockIdx.x * 128;
    const int NC = K >> 6;

    float c[2][4][4] = {};

    const int al_r  = lid & 15;
    const int al_k  = (lid >> 4) & 1;
    const int bl_r  = (lid & 7) + ((lid >> 4) << 3);
    const int bl_k  = (lid >> 3) & 1;

    auto load_stage = [&](int st, int ck) {
        const unsigned sdst = sbase + (unsigned)st * STAGE;
        const int k0 = ck << 6;
        #pragma unroll
        for (int sp = 0; sp < 2; sp++) {
            #pragma unroll
            for (int i = 0; i < 2; i++) {
                int idx = i * 256 + tid;
                int row = idx >> 3, g = idx & 7;
                const __nv_bfloat16* gs = AP[sp] + (rm0 + row) * (size_t)K + k0 + g * 8;
                unsigned d = sdst + (unsigned)sp * TA + swz((unsigned)(row * 128 + g * 16));
                CP_ASYNC16(d, gs);
            }
        }
        #pragma unroll
        for (int sp = 0; sp < 2; sp++) {
            #pragma unroll
            for (int i = 0; i < 4; i++) {
                int idx = i * 256 + tid;
                int row = idx >> 3, g = idx & 7;
                const __nv_bfloat16* gs = BP[sp] + (rn0 + row) * (size_t)K + k0 + g * 8;
                unsigned d = sdst + 2 * TA + (unsigned)sp * TB +
                             swz((unsigned)(row * 128 + g * 16));
                CP_ASYNC16(d, gs);
            }
        }
    };

    load_stage(0, 0); CP_COMMIT();

    for (int ck = 0; ck < NC; ck++) {
        if (ck + 1 < NC) {
            load_stage((ck + 1) & 1, ck + 1);
            CP_COMMIT();
            CP_WAIT1();
        } else {
            CP_WAIT0();
        }
        __syncthreads();

        const unsigned sb2 = sbase + (unsigned)(ck & 1) * STAGE;
        #pragma unroll
        for (int ks = 0; ks < 4; ks++) {
            unsigned af[2][2][4];
            unsigned bf[2][4][2];
            #pragma unroll
            for (int sp = 0; sp < 2; sp++) {
                #pragma unroll
                for (int mt = 0; mt < 2; mt++) {
                    unsigned addr = sb2 + (unsigned)sp * TA +
                        swz((unsigned)((wm * 32 + mt * 16 + al_r) * 128 + ks * 32 + al_k * 16));
                    ldsm4(af[sp][mt], addr);
                }
                #pragma unroll
                for (int np = 0; np < 2; np++) {
                    unsigned r[4];
                    unsigned addr = sb2 + 2 * TA + (unsigned)sp * TB +
                        swz((unsigned)((wn * 32 + np * 16 + bl_r) * 128 + ks * 32 + bl_k * 16));
                    ldsm4(r, addr);
                    bf[sp][2 * np][0] = r[0]; bf[sp][2 * np][1] = r[1];
                    bf[sp][2 * np + 1][0] = r[2]; bf[sp][2 * np + 1][1] = r[3];
                }
            }
            #pragma unroll
            for (int tm = 0; tm < 3; tm++) {
                const int i = (tm == 2) ? 1 : 0;
                const int j = (tm == 1) ? 1 : 0;
                #pragma unroll
                for (int mt = 0; mt < 2; mt++)
                    #pragma unroll
                    for (int nt = 0; nt < 4; nt++)
                        mma_bf16(c[mt][nt], af[i][mt], bf[j][nt]);
            }
        }
        __syncthreads();
    }

    const int qr = lid >> 2;
    const int qc = (lid & 3) * 2;
    #pragma unroll
    for (int mt = 0; mt < 2; mt++) {
        #pragma unroll
        for (int nt = 0; nt < 4; nt++) {
            size_t gr = rm0 + wm * 32 + mt * 16 + qr;
            int gc = (int)rn0 + wn * 32 + nt * 8 + qc;
            #pragma unroll
            for (int half = 0; half < 2; half++) {
                float v0 = c[mt][nt][2 * half + 0];
                float v1 = c[mt][nt][2 * half + 1];
                size_t o = zb * sC + (gr + half * 8) * (size_t)ldc + gc;
                __nv_bfloat162 hv, lv;
                hv.x = __float2bfloat16(v0);
                hv.y = __float2bfloat16(v1);
                lv.x = __float2bfloat16(v0 - __bfloat162float(hv.x));
                lv.y = __float2bfloat16(v1 - __bfloat162float(hv.y));
                *reinterpret_cast<__nv_bfloat162*>(Ch + o) = hv;
                *reinterpret_cast<__nv_bfloat162*>(Cl + o) = lv;
            }
        }
    }
}

// ---------------------------------------------------------------------------
// Dual-B GEMM with fused split-softmax epilogue. CTA tile 64x128, 2-stage
// (80 KB/stage). c1 = rf@Nt^T, c2 = rf@qe2^T. Per row: partial softmax over
// this CTA's 128 t-values -> one float4 (m, den, num, 0) per (row, t-slice).
// ---------------------------------------------------------------------------
__global__ void __launch_bounds__(256) gemm_dual(
    const __nv_bfloat16* __restrict__ A0, const __nv_bfloat16* __restrict__ A1,
    const __nv_bfloat16* __restrict__ B0, const __nv_bfloat16* __restrict__ B1,
    const __nv_bfloat16* __restrict__ C0, const __nv_bfloat16* __restrict__ C1,
    const float* __restrict__ qv, const float* __restrict__ y1,
    float4* __restrict__ part,
    int K, size_t sA, size_t sB)
{
    constexpr unsigned TA = 64 * 128;     // 8 KB
    constexpr unsigned TB = 128 * 128;    // 16 KB
    constexpr unsigned STAGE = 2 * TA + 4 * TB;   // 80 KB

    extern __shared__ char smem[];
    const unsigned sbase = smem_u32(smem);

    const int tid = threadIdx.x;
    const int lid = tid & 31;
    const int wid = tid >> 5;
    const int wm = wid & 1;
    const int wn = wid >> 1;

    const size_t zb = blockIdx.z;
    const __nv_bfloat16* AP[2] = { A0 + zb * sA, A1 + zb * sA };
    const __nv_bfloat16* BP[4] = { B0 + zb * sB, B1 + zb * sB,
                                   C0 + zb * sB, C1 + zb * sB };
    const size_t rm0 = (size_t)blockIdx.y * 64;
    const size_t rn0 = (size_t)blockIdx.x * 128;
    const int NC = K >> 6;

    float c1[2][4][4] = {};
    float c2[2][4][4] = {};

    const int al_r  = lid & 15;
    const int al_k  = (lid >> 4) & 1;
    const int bl_r  = (lid & 7) + ((lid >> 4) << 3);
    const int bl_k  = (lid >> 3) & 1;

    auto load_stage = [&](int st, int ck) {
        const unsigned sdst = sbase + (unsigned)st * STAGE;
        const int k0 = ck << 6;
        #pragma unroll
        for (int sp = 0; sp < 2; sp++) {
            #pragma unroll
            for (int i = 0; i < 2; i++) {
                int idx = i * 256 + tid;
                int row = idx >> 3, g = idx & 7;
                const __nv_bfloat16* gs = AP[sp] + (rm0 + row) * (size_t)K + k0 + g * 8;
                unsigned d = sdst + (unsigned)sp * TA + swz((unsigned)(row * 128 + g * 16));
                CP_ASYNC16(d, gs);
            }
        }
        #pragma unroll
        for (int t4 = 0; t4 < 4; t4++) {
            #pragma unroll
            for (int i = 0; i < 4; i++) {
                int idx = i * 256 + tid;
                int row = idx >> 3, g = idx & 7;
                const __nv_bfloat16* gs = BP[t4] + (rn0 + row) * (size_t)K + k0 + g * 8;
                unsigned d = sdst + 2 * TA + (unsigned)t4 * TB +
                             swz((unsigned)(row * 128 + g * 16));
                CP_ASYNC16(d, gs);
            }
        }
    };

    load_stage(0, 0); CP_COMMIT();

    for (int ck = 0; ck < NC; ck++) {
        if (ck + 1 < NC) {
            load_stage((ck + 1) & 1, ck + 1);
            CP_COMMIT();
            CP_WAIT1();
        } else {
            CP_WAIT0();
        }
        __syncthreads();

        const unsigned sb2 = sbase + (unsigned)(ck & 1) * STAGE;
        #pragma unroll
        for (int ks = 0; ks < 4; ks++) {
            unsigned af[2][2][4];
            #pragma unroll
            for (int sp = 0; sp < 2; sp++)
                #pragma unroll
                for (int mt = 0; mt < 2; mt++) {
                    unsigned addr = sb2 + (unsigned)sp * TA +
                        swz((unsigned)((wm * 32 + mt * 16 + al_r) * 128 + ks * 32 + al_k * 16));
                    ldsm4(af[sp][mt], addr);
                }
            {
                unsigned bf[2][4][2];
                #pragma unroll
                for (int sp = 0; sp < 2; sp++)
                    #pragma unroll
                    for (int np = 0; np < 2; np++) {
                        unsigned r[4];
                        unsigned addr = sb2 + 2 * TA + (unsigned)sp * TB +
                            swz((unsigned)((wn * 32 + np * 16 + bl_r) * 128 + ks * 32 + bl_k * 16));
                        ldsm4(r, addr);
                        bf[sp][2 * np][0] = r[0]; bf[sp][2 * np][1] = r[1];
                        bf[sp][2 * np + 1][0] = r[2]; bf[sp][2 * np + 1][1] = r[3];
                    }
                #pragma unroll
                for (int tm = 0; tm < 3; tm++) {
                    const int i = (tm == 2) ? 1 : 0;
                    const int j = (tm == 1) ? 1 : 0;
                    #pragma unroll
                    for (int mt = 0; mt < 2; mt++)
                        #pragma unroll
                        for (int nt = 0; nt < 4; nt++)
                            mma_bf16(c1[mt][nt], af[i][mt], bf[j][nt]);
                }
            }
            {
                unsigned bf[2][4][2];
                #pragma unroll
                for (int sp = 0; sp < 2; sp++)
                    #pragma unroll
                    for (int np = 0; np < 2; np++) {
                        unsigned r[4];
                        unsigned addr = sb2 + 2 * TA + (unsigned)(2 + sp) * TB +
                            swz((unsigned)((wn * 32 + np * 16 + bl_r) * 128 + ks * 32 + bl_k * 16));
                        ldsm4(r, addr);
                        bf[sp][2 * np][0] = r[0]; bf[sp][2 * np][1] = r[1];
                        bf[sp][2 * np + 1][0] = r[2]; bf[sp][2 * np + 1][1] = r[3];
                    }
                #pragma unroll
                for (int tm = 0; tm < 3; tm++) {
                    const int i = (tm == 2) ? 1 : 0;
                    const int j = (tm == 1) ? 1 : 0;
                    #pragma unroll
                    for (int mt = 0; mt < 2; mt++)
                        #pragma unroll
                        for (int nt = 0; nt < 4; nt++)
                            mma_bf16(c2[mt][nt], af[i][mt], bf[j][nt]);
                }
            }
        }
        __syncthreads();
    }

    // ---- Fused split-softmax epilogue ----
    const int qr = lid >> 2;
    const int qc = (lid & 3) * 2;
    const size_t boff = zb * TT;
    const int tbase = (int)rn0 + wn * 32;

    float2 qvv[4], y1v[4];
    #pragma unroll
    for (int nt = 0; nt < 4; nt++) {
        int t0 = tbase + nt * 8 + qc;
        qvv[nt] = *reinterpret_cast<const float2*>(qv + boff + t0);
        y1v[nt] = *reinterpret_cast<const float2*>(y1 + boff + t0);
    }

    float* sp = reinterpret_cast<float*>(smem);   // [64 rows][4 wn][3] = 3 KB

    #pragma unroll
    for (int mt = 0; mt < 2; mt++) {
        #pragma unroll
        for (int half = 0; half < 2; half++) {
            float sv[8];
            float m = -1e30f;
            #pragma unroll
            for (int nt = 0; nt < 4; nt++) {
                sv[2 * nt]     = c1[mt][nt][2 * half]     + qvv[nt].x;
                sv[2 * nt + 1] = c1[mt][nt][2 * half + 1] + qvv[nt].y;
                m = fmaxf(m, fmaxf(sv[2 * nt], sv[2 * nt + 1]));
            }
            float den = 0.f, num = 0.f;
            #pragma unroll
            for (int nt = 0; nt < 4; nt++) {
                float e0 = __expf(sv[2 * nt] - m);
                float e1 = __expf(sv[2 * nt + 1] - m);
                den += e0 + e1;
                num = fmaf(e0, y1v[nt].x + c2[mt][nt][2 * half], num);
                num = fmaf(e1, y1v[nt].y + c2[mt][nt][2 * half + 1], num);
            }
            // merge across the 4 qc-lanes (lid^1, lid^2)
            #pragma unroll
            for (int o = 1; o <= 2; o <<= 1) {
                float mo = __shfl_xor_sync(0xffffffffu, m, o);
                float dn = __shfl_xor_sync(0xffffffffu, den, o);
                float no = __shfl_xor_sync(0xffffffffu, num, o);
                float mn = fmaxf(m, mo);
                float sa = __expf(m - mn), sb = __expf(mo - mn);
                den = den * sa + dn * sb;
                num = num * sa + no * sb;
                m = mn;
            }
            if ((lid & 3) == 0) {
                int lr = wm * 32 + mt * 16 + qr + half * 8;
                sp[(lr * 4 + wn) * 3 + 0] = m;
                sp[(lr * 4 + wn) * 3 + 1] = den;
                sp[(lr * 4 + wn) * 3 + 2] = num;
            }
        }
    }
    __syncthreads();
    if (tid < 64) {
        float m = -1e30f;
        #pragma unroll
        for (int w = 0; w < 4; w++) m = fmaxf(m, sp[(tid * 4 + w) * 3]);
        float den = 0.f, num = 0.f;
        #pragma unroll
        for (int w = 0; w < 4; w++) {
            float s = __expf(sp[(tid * 4 + w) * 3] - m);
            den = fmaf(sp[(tid * 4 + w) * 3 + 1], s, den);
            num = fmaf(sp[(tid * 4 + w) * 3 + 2], s, num);
        }
        size_t row = zb * RR + rm0 + tid;
        part[row * 4 + blockIdx.x] = make_float4(m, den, num, 0.f);
    }
}

// ---------------------------------------------------------------------------
// Finalize: merge 4 softmax partials per row; out = rd0 + num/den + bs
// ---------------------------------------------------------------------------
__global__ void __launch_bounds__(256) finalize_k(
    const float4* __restrict__ part, const float* __restrict__ rd0,
    const float* __restrict__ bs, float* __restrict__ out)
{
    int i = blockIdx.x * 256 + threadIdx.x;
    float4 p0 = part[(size_t)i * 4 + 0];
    float4 p1 = part[(size_t)i * 4 + 1];
    float4 p2 = part[(size_t)i * 4 + 2];
    float4 p3 = part[(size_t)i * 4 + 3];
    float m = fmaxf(fmaxf(p0.x, p1.x), fmaxf(p2.x, p3.x));
    float s0 = __expf(p0.x - m), s1 = __expf(p1.x - m);
    float s2 = __expf(p2.x - m), s3 = __expf(p3.x - m);
    float den = p0.y * s0 + p1.y * s1 + p2.y * s2 + p3.y * s3;
    float num = p0.z * s0 + p1.z * s1 + p2.z * s2 + p3.z * s3;
    out[i] = rd0[i] + num / den + bs[0];
}

// ---------------------------------------------------------------------------
// Merged weight split: blocks [0,512) handle Wr, [512,1024) handle Wq.
// ---------------------------------------------------------------------------
__global__ void __launch_bounds__(256) split2w_k(
    const float4* __restrict__ Wr, const float4* __restrict__ Wq,
    __nv_bfloat16* __restrict__ Wr_h, __nv_bfloat16* __restrict__ Wr_l,
    __nv_bfloat16* __restrict__ Wq_h, __nv_bfloat16* __restrict__ Wq_l)
{
    const int n4 = DD * HH / 4;
    const bool second = blockIdx.x >= 512;
    const float4* x = second ? Wq : Wr;
    __nv_bfloat16* h = second ? Wq_h : Wr_h;
    __nv_bfloat16* l = second ? Wq_l : Wr_l;
    int b0 = second ? (blockIdx.x - 512) : blockIdx.x;
    for (int i = b0 * 256 + threadIdx.x; i < n4; i += 512 * 256) {
        float4 v = x[i];
        float a[4] = {v.x, v.y, v.z, v.w};
        __nv_bfloat16 hh[4], ll[4];
        #pragma unroll
        for (int k = 0; k < 4; k++) {
            hh[k] = __float2bfloat16(a[k]);
            ll[k] = __float2bfloat16(a[k] - __bfloat162float(hh[k]));
        }
        __nv_bfloat162 p0, p1;
        p0.x = hh[0]; p0.y = hh[1]; p1.x = hh[2]; p1.y = hh[3];
        reinterpret_cast<__nv_bfloat162*>(h)[2 * i] = p0;
        reinterpret_cast<__nv_bfloat162*>(h)[2 * i + 1] = p1;
        p0.x = ll[0]; p0.y = ll[1]; p1.x = ll[2]; p1.y = ll[3];
        reinterpret_cast<__nv_bfloat162*>(l)[2 * i] = p0;
        reinterpret_cast<__nv_bfloat162*>(l)[2 * i + 1] = p1;
    }
}

// ---------------------------------------------------------------------------
// region prep: one CTA per (b,r) row. Writes rf_h/rf_l; computes rd0 = row.Ws0.
// ---------------------------------------------------------------------------
__global__ void __launch_bounds__(256) region_prep_k(
    const float* __restrict__ region, const float* __restrict__ Ws0,
    __nv_bfloat16* __restrict__ rf_h, __nv_bfloat16* __restrict__ rf_l,
    float* __restrict__ rd0)
{
    size_t row = blockIdx.x;
    int t = threadIdx.x;
    float4 a = *reinterpret_cast<const float4*>(region + row * DD + t * 4);
    float4 w = *reinterpret_cast<const float4*>(Ws0 + t * 4);

    __nv_bfloat162 h0, h1, l0, l1;
    h0.x = __float2bfloat16(a.x); h0.y = __float2bfloat16(a.y);
    h1.x = __float2bfloat16(a.z); h1.y = __float2bfloat16(a.w);
    l0.x = __float2bfloat16(a.x - __bfloat162float(h0.x));
    l0.y = __float2bfloat16(a.y - __bfloat162float(h0.y));
    l1.x = __float2bfloat16(a.z - __bfloat162float(h1.x));
    l1.y = __float2bfloat16(a.w - __bfloat162float(h1.y));
    reinterpret_cast<__nv_bfloat162*>(rf_h + row * DD)[2 * t] = h0;
    reinterpret_cast<__nv_bfloat162*>(rf_h + row * DD)[2 * t + 1] = h1;
    reinterpret_cast<__nv_bfloat162*>(rf_l + row * DD)[2 * t] = l0;
    reinterpret_cast<__nv_bfloat162*>(rf_l + row * DD)[2 * t + 1] = l1;

    float p = a.x * w.x + a.y * w.y + a.z * w.z + a.w * w.w;
    __shared__ float red[8];
    #pragma unroll
    for (int o = 16; o; o >>= 1) p += __shfl_xor_sync(0xffffffffu, p, o);
    if ((t & 31) == 0) red[t >> 5] = p;
    __syncthreads();
    if (t == 0) {
        float s = 0.f;
        #pragma unroll
        for (int i = 0; i < 8; i++) s += red[i];
        rd0[row] = s;
    }
}

// ---------------------------------------------------------------------------
// query prep: one CTA per (b,t) row. Writes qe_h/l and qe2_h/l (= qe*Ws2);
// computes qv = row.v and y1 = row.Ws1.
// ---------------------------------------------------------------------------
__global__ void __launch_bounds__(256) query_prep_k(
    const float* __restrict__ query, const float* __restrict__ v,
    const float* __restrict__ Ws1, const float* __restrict__ Ws2,
    __nv_bfloat16* __restrict__ qe_h, __nv_bfloat16* __restrict__ qe_l,
    __nv_bfloat16* __restrict__ qe2_h, __nv_bfloat16* __restrict__ qe2_l,
    float* __restrict__ qv, float* __restrict__ y1)
{
    size_t row = blockIdx.x;
    int t = threadIdx.x;
    float4 a = *reinterpret_cast<const float4*>(query + row * DD + t * 4);
    float4 vv = *reinterpret_cast<const float4*>(v + t * 4);
    float4 w1 = *reinterpret_cast<const float4*>(Ws1 + t * 4);
    float4 w2 = *reinterpret_cast<const float4*>(Ws2 + t * 4);

    __nv_bfloat162 h0, h1, l0, l1;
    h0.x = __float2bfloat16(a.x); h0.y = __float2bfloat16(a.y);
    h1.x = __float2bfloat16(a.z); h1.y = __float2bfloat16(a.w);
    l0.x = __float2bfloat16(a.x - __bfloat162float(h0.x));
    l0.y = __float2bfloat16(a.y - __bfloat162float(h0.y));
    l1.x = __float2bfloat16(a.z - __bfloat162float(h1.x));
    l1.y = __float2bfloat16(a.w - __bfloat162float(h1.y));
    reinterpret_cast<__nv_bfloat162*>(qe_h + row * DD)[2 * t] = h0;
    reinterpret_cast<__nv_bfloat162*>(qe_h + row * DD)[2 * t + 1] = h1;
    reinterpret_cast<__nv_bfloat162*>(qe_l + row * DD)[2 * t] = l0;
    reinterpret_cast<__nv_bfloat162*>(qe_l + row * DD)[2 * t + 1] = l1;

    float b0 = a.x * w2.x, b1 = a.y * w2.y, b2 = a.z * w2.z, b3 = a.w * w2.w;
    h0.x = __float2bfloat16(b0); h0.y = __float2bfloat16(b1);
    h1.x = __float2bfloat16(b2); h1.y = __float2bfloat16(b3);
    l0.x = __float2bfloat16(b0 - __bfloat162float(h0.x));
    l0.y = __float2bfloat16(b1 - __bfloat162float(h0.y));
    l1.x = __float2bfloat16(b2 - __bfloat162float(h1.x));
    l1.y = __float2bfloat16(b3 - __bfloat162float(h1.y));
    reinterpret_cast<__nv_bfloat162*>(qe2_h + row * DD)[2 * t] = h0;
    reinterpret_cast<__nv_bfloat162*>(qe2_h + row * DD)[2 * t + 1] = h1;
    reinterpret_cast<__nv_bfloat162*>(qe2_l + row * DD)[2 * t] = l0;
    reinterpret_cast<__nv_bfloat162*>(qe2_l + row * DD)[2 * t + 1] = l1;

    float p = a.x * vv.x + a.y * vv.y + a.z * vv.z + a.w * vv.w;
    float q = a.x * w1.x + a.y * w1.y + a.z * w1.z + a.w * w1.w;
    __shared__ float red[16];
    #pragma unroll
    for (int o = 16; o; o >>= 1) {
        p += __shfl_xor_sync(0xffffffffu, p, o);
        q += __shfl_xor_sync(0xffffffffu, q, o);
    }
    if ((t & 31) == 0) { red[t >> 5] = p; red[8 + (t >> 5)] = q; }
    __syncthreads();
    if (t == 0) {
        float s = 0.f, s2 = 0.f;
        #pragma unroll
        for (int i = 0; i < 8; i++) { s += red[i]; s2 += red[8 + i]; }
        qv[row] = s;
        y1[row] = s2;
    }
}

// ---------------------------------------------------------------------------
// v[d] = sum_h Wq[d,h] * br[h]
// ---------------------------------------------------------------------------
__global__ void __launch_bounds__(256) matvec_k(
    const float* __restrict__ W, const float* __restrict__ b,
    float* __restrict__ v, int H)
{
    const float* row = W + (size_t)blockIdx.x * H;
    int t = threadIdx.x;
    float p = 0.f;
    for (int h = t * 4; h < H; h += 1024) {
        float4 wv = *reinterpret_cast<const float4*>(row + h);
        float4 bv = *reinterpret_cast<const float4*>(b + h);
        p = fmaf(wv.x, bv.x, p); p = fmaf(wv.y, bv.y, p);
        p = fmaf(wv.z, bv.z, p); p = fmaf(wv.w, bv.w, p);
    }
    __shared__ float red[8];
    #pragma unroll
    for (int o = 16; o; o >>= 1) p += __shfl_xor_sync(0xffffffffu, p, o);
    if ((t & 31) == 0) red[t >> 5] = p;
    __syncthreads();
    if (t == 0) {
        float s = 0.f;
        #pragma unroll
        for (int i = 0; i < 8; i++) s += red[i];
        v[blockIdx.x] = s;
    }
}

// ---------------------------------------------------------------------------
extern "C" void kernel_launch(void* const* d_in, const int* in_sizes, int n_in,
                              void* d_out, int out_size)
{
    const float* region = (const float*)d_in[0];
    const float* query  = (const float*)d_in[1];
    const float* Wr     = (const float*)d_in[2];
    const float* br     = (const float*)d_in[3];
    const float* Wq     = (const float*)d_in[4];
    const float* bq     = (const float*)d_in[5];
    const float* Ws     = (const float*)d_in[6];
    const float* bs     = (const float*)d_in[7];
    float* out = (float*)d_out;
    (void)bq;  // softmax-invariant terms drop out

    __nv_bfloat16 *Wr_h, *Wr_l, *Wq_h, *Wq_l, *M2_h, *M2_l;
    __nv_bfloat16 *rf_h, *rf_l, *qe_h, *qe_l, *qe2_h, *qe2_l, *Nt_h, *Nt_l;
    float4 *partb;
    float *v, *qv, *y1, *rd0;
    cudaGetSymbolAddress((void**)&Wr_h, g_Wr_h);
    cudaGetSymbolAddress((void**)&Wr_l, g_Wr_l);
    cudaGetSymbolAddress((void**)&Wq_h, g_Wq_h);
    cudaGetSymbolAddress((void**)&Wq_l, g_Wq_l);
    cudaGetSymbolAddress((void**)&M2_h, g_M2_h);
    cudaGetSymbolAddress((void**)&M2_l, g_M2_l);
    cudaGetSymbolAddress((void**)&rf_h, g_rf_h);
    cudaGetSymbolAddress((void**)&rf_l, g_rf_l);
    cudaGetSymbolAddress((void**)&qe_h, g_qe_h);
    cudaGetSymbolAddress((void**)&qe_l, g_qe_l);
    cudaGetSymbolAddress((void**)&qe2_h, g_qe2_h);
    cudaGetSymbolAddress((void**)&qe2_l, g_qe2_l);
    cudaGetSymbolAddress((void**)&Nt_h, g_Nt_h);
    cudaGetSymbolAddress((void**)&Nt_l, g_Nt_l);
    cudaGetSymbolAddress((void**)&partb, g_part);
    cudaGetSymbolAddress((void**)&v, g_v);
    cudaGetSymbolAddress((void**)&qv, g_qv);
    cudaGetSymbolAddress((void**)&y1, g_y1);
    cudaGetSymbolAddress((void**)&rd0, g_rd0);

    const int SMEM1 = 2 * (2 * 8192 + 2 * 16384);       // 98304 (2-stage, 48KB) -> 2 CTAs/SM
    const int SMEMD = 2 * (2 * 8192 + 4 * 16384);       // 163840 (2-stage, 80KB)
    cudaFuncSetAttribute(gemm_mma1, cudaFuncAttributeMaxDynamicSharedMemorySize, SMEM1);
    cudaFuncSetAttribute(gemm_dual, cudaFuncAttributeMaxDynamicSharedMemorySize, SMEMD);

    // 1) merged weight splits + bias matvec
    split2w_k<<<1024, 256>>>((const float4*)Wr, (const float4*)Wq,
                             Wr_h, Wr_l, Wq_h, Wq_l);
    matvec_k<<<DD, 256>>>(Wq, br, v, HH);
    // 2) fused activation prep (single pass over region and query)
    region_prep_k<<<BB * RR, 256>>>(region, Ws, rf_h, rf_l, rd0);
    query_prep_k<<<BB * TT, 256>>>(query, v, Ws + DD, Ws + 2 * DD,
                                   qe_h, qe_l, qe2_h, qe2_l, qv, y1);
    // 3) M2[d,e] = sum_h Wr[d,h] Wq[e,h]  (e contiguous), split output
    gemm_mma1<<<dim3(DD / 128, DD / 64, 1), 256, SMEM1>>>(
        Wr_h, Wr_l, Wq_h, Wq_l, M2_h, M2_l, HH, 0, 0, 0, DD);
    // 4) Nt[b][t,d] = sum_e qe[b,t,e] M2[d,e]  (d contiguous), split output
    gemm_mma1<<<dim3(DD / 128, TT / 64, BB), 256, SMEM1>>>(
        qe_h, qe_l, M2_h, M2_l, Nt_h, Nt_l,
        DD, (size_t)TT * DD, 0, (size_t)TT * DD, DD);
    // 5) dual GEMM with fused split-softmax epilogue -> partials
    gemm_dual<<<dim3(TT / 128, RR / 64, BB), 256, SMEMD>>>(
        rf_h, rf_l, Nt_h, Nt_l, qe2_h, qe2_l, qv, y1, partb,
        DD, (size_t)RR * DD, (size_t)TT * DD);
    // 6) finalize: merge partials -> out
    finalize_k<<<BB * RR / 256, 256>>>(partb, rd0, bs, out);
}

// round 16
// speedup vs baseline: 1.1578x; 1.0154x over previous
#include <cuda_runtime.h>
#include <cuda_bf16.h>

#define BB 16
#define RR 1024
#define TT 512
#define DD 1024
#define HH 1024

// ---------------------------------------------------------------------------
// Scratch (device globals — allocations are forbidden)
// ---------------------------------------------------------------------------
__device__ __nv_bfloat16 g_Wr_h[DD * HH], g_Wr_l[DD * HH];
__device__ __nv_bfloat16 g_Wq_h[DD * HH], g_Wq_l[DD * HH];
__device__ __nv_bfloat16 g_M2_h[DD * DD], g_M2_l[DD * DD];       // M2[d,e] = sum_h Wr[d,h]Wq[e,h]
__device__ __nv_bfloat16 g_rf_h[(size_t)BB * RR * DD], g_rf_l[(size_t)BB * RR * DD];
__device__ __nv_bfloat16 g_qe_h[(size_t)BB * TT * DD], g_qe_l[(size_t)BB * TT * DD];
__device__ __nv_bfloat16 g_qe2_h[(size_t)BB * TT * DD], g_qe2_l[(size_t)BB * TT * DD]; // qe*Ws2
__device__ __nv_bfloat16 g_Nt_h[(size_t)BB * TT * DD], g_Nt_l[(size_t)BB * TT * DD];   // Nt[b][t,d]
__device__ float4        g_part[(size_t)BB * RR * 4];   // (m, den, num, pad) per t-slice
__device__ float         g_v[DD];
__device__ float         g_qv[BB * TT];
__device__ float         g_y1[BB * TT];
__device__ float         g_rd0[BB * RR];

// ---------------------------------------------------------------------------
// PTX helpers (sm_80-level features only: ldmatrix, cp.async, mma.sync)
// ---------------------------------------------------------------------------
__device__ __forceinline__ unsigned smem_u32(const void* p) {
    unsigned a;
    asm("{ .reg .u64 t; cvta.to.shared.u64 t, %1; cvt.u32.u64 %0, t; }" : "=r"(a) : "l"(p));
    return a;
}

#define CP_ASYNC16(dst, src) \
    asm volatile("cp.async.cg.shared.global [%0], [%1], 16;" :: "r"(dst), "l"(src))
#define CP_COMMIT() asm volatile("cp.async.commit_group;" ::: "memory")
#define CP_WAIT0()  asm volatile("cp.async.wait_group 0;" ::: "memory")
#define CP_WAIT1()  asm volatile("cp.async.wait_group 1;" ::: "memory")

__device__ __forceinline__ void ldsm4(unsigned* r, unsigned addr) {
    asm volatile("ldmatrix.sync.aligned.m8n8.x4.shared.b16 {%0,%1,%2,%3}, [%4];"
                 : "=r"(r[0]), "=r"(r[1]), "=r"(r[2]), "=r"(r[3]) : "r"(addr));
}

__device__ __forceinline__ void mma_bf16(float* c, const unsigned* a, const unsigned* b) {
    asm volatile(
        "mma.sync.aligned.m16n8k16.row.col.f32.bf16.bf16.f32 "
        "{%0,%1,%2,%3}, {%4,%5,%6,%7}, {%8,%9}, {%0,%1,%2,%3};"
        : "+f"(c[0]), "+f"(c[1]), "+f"(c[2]), "+f"(c[3])
        : "r"(a[0]), "r"(a[1]), "r"(a[2]), "r"(a[3]), "r"(b[0]), "r"(b[1]));
}

__device__ __forceinline__ unsigned swz(unsigned off) {
    return off ^ ((off >> 3) & 0x70);
}

// ---------------------------------------------------------------------------
// Split-bf16 GEMM, CTA tile 64x128 (8 warps = 2M x 4N, warp tile 32x32).
// 3 terms: hh + hl + lh. K chunks of 64 bf16 (SW128), 2-stage cp.async,
// 2 CTAs/SM (cross-CTA latency hiding). Split hi/lo bf16 output (M2, Nt).
// ---------------------------------------------------------------------------
__global__ void __launch_bounds__(256, 2) gemm_mma1(
    const __nv_bfloat16* __restrict__ A0, const __nv_bfloat16* __restrict__ A1,
    const __nv_bfloat16* __restrict__ B0, const __nv_bfloat16* __restrict__ B1,
    __nv_bfloat16* __restrict__ Ch, __nv_bfloat16* __restrict__ Cl,
    int K, size_t sA, size_t sB, size_t sC, int ldc)
{
    constexpr unsigned TA = 64 * 128;     // 8 KB per A split tile
    constexpr unsigned TB = 128 * 128;    // 16 KB per B split tile
    constexpr unsigned STAGE = 2 * TA + 2 * TB;   // 48 KB

    extern __shared__ char smem[];
    const unsigned sbase = smem_u32(smem);

    const int tid = threadIdx.x;
    const int lid = tid & 31;
    const int wid = tid >> 5;
    const int wm = wid & 1;
    const int wn = wid >> 1;

    const size_t zb = blockIdx.z;
    const __nv_bfloat16* AP[2] = { A0 + zb * sA, A1 + zb * sA };
    const __nv_bfloat16* BP[2] = { B0 + zb * sB, B1 + zb * sB };
    const size_t rm0 = (size_t)blockIdx.y * 64;
    const size_t rn0 = (size_t)blockIdx.x * 128;
    const int NC = K >> 6;

    float c[2][4][4] = {};

    const int al_r  = lid & 15;
    const int al_k  = (lid >> 4) & 1;
    const int bl_r  = (lid & 7) + ((lid >> 4) << 3);
    const int bl_k  = (lid >> 3) & 1;

    auto load_stage = [&](int st, int ck) {
        const unsigned sdst = sbase + (unsigned)st * STAGE;
        const int k0 = ck << 6;
        #pragma unroll
        for (int sp = 0; sp < 2; sp++) {
            #pragma unroll
            for (int i = 0; i < 2; i++) {
                int idx = i * 256 + tid;
                int row = idx >> 3, g = idx & 7;
                const __nv_bfloat16* gs = AP[sp] + (rm0 + row) * (size_t)K + k0 + g * 8;
                unsigned d = sdst + (unsigned)sp * TA + swz((unsigned)(row * 128 + g * 16));
                CP_ASYNC16(d, gs);
            }
        }
        #pragma unroll
        for (int sp = 0; sp < 2; sp++) {
            #pragma unroll
            for (int i = 0; i < 4; i++) {
                int idx = i * 256 + tid;
                int row = idx >> 3, g = idx & 7;
                const __nv_bfloat16* gs = BP[sp] + (rn0 + row) * (size_t)K + k0 + g * 8;
                unsigned d = sdst + 2 * TA + (unsigned)sp * TB +
                             swz((unsigned)(row * 128 + g * 16));
                CP_ASYNC16(d, gs);
            }
        }
    };

    load_stage(0, 0); CP_COMMIT();

    for (int ck = 0; ck < NC; ck++) {
        if (ck + 1 < NC) {
            load_stage((ck + 1) & 1, ck + 1);
            CP_COMMIT();
            CP_WAIT1();
        } else {
            CP_WAIT0();
        }
        __syncthreads();

        const unsigned sb2 = sbase + (unsigned)(ck & 1) * STAGE;
        #pragma unroll
        for (int ks = 0; ks < 4; ks++) {
            unsigned af[2][2][4];
            unsigned bf[2][4][2];
            #pragma unroll
            for (int sp = 0; sp < 2; sp++) {
                #pragma unroll
                for (int mt = 0; mt < 2; mt++) {
                    unsigned addr = sb2 + (unsigned)sp * TA +
                        swz((unsigned)((wm * 32 + mt * 16 + al_r) * 128 + ks * 32 + al_k * 16));
                    ldsm4(af[sp][mt], addr);
                }
                #pragma unroll
                for (int np = 0; np < 2; np++) {
                    unsigned r[4];
                    unsigned addr = sb2 + 2 * TA + (unsigned)sp * TB +
                        swz((unsigned)((wn * 32 + np * 16 + bl_r) * 128 + ks * 32 + bl_k * 16));
                    ldsm4(r, addr);
                    bf[sp][2 * np][0] = r[0]; bf[sp][2 * np][1] = r[1];
                    bf[sp][2 * np + 1][0] = r[2]; bf[sp][2 * np + 1][1] = r[3];
                }
            }
            #pragma unroll
            for (int tm = 0; tm < 3; tm++) {
                const int i = (tm == 2) ? 1 : 0;
                const int j = (tm == 1) ? 1 : 0;
                #pragma unroll
                for (int mt = 0; mt < 2; mt++)
                    #pragma unroll
                    for (int nt = 0; nt < 4; nt++)
                        mma_bf16(c[mt][nt], af[i][mt], bf[j][nt]);
            }
        }
        __syncthreads();
    }

    const int qr = lid >> 2;
    const int qc = (lid & 3) * 2;
    #pragma unroll
    for (int mt = 0; mt < 2; mt++) {
        #pragma unroll
        for (int nt = 0; nt < 4; nt++) {
            size_t gr = rm0 + wm * 32 + mt * 16 + qr;
            int gc = (int)rn0 + wn * 32 + nt * 8 + qc;
            #pragma unroll
            for (int half = 0; half < 2; half++) {
                float v0 = c[mt][nt][2 * half + 0];
                float v1 = c[mt][nt][2 * half + 1];
                size_t o = zb * sC + (gr + half * 8) * (size_t)ldc + gc;
                __nv_bfloat162 hv, lv;
                hv.x = __float2bfloat16(v0);
                hv.y = __float2bfloat16(v1);
                lv.x = __float2bfloat16(v0 - __bfloat162float(hv.x));
                lv.y = __float2bfloat16(v1 - __bfloat162float(hv.y));
                *reinterpret_cast<__nv_bfloat162*>(Ch + o) = hv;
                *reinterpret_cast<__nv_bfloat162*>(Cl + o) = lv;
            }
        }
    }
}

// ---------------------------------------------------------------------------
// Dual-B GEMM with fused split-softmax epilogue. CTA tile 64x128,
// SINGLE-stage smem (80 KB) at 2 CTAs/SM: cross-CTA overlap hides the
// per-chunk load latency (R15 lesson). c1 = rf@Nt^T, c2 = rf@qe2^T.
// Per row: partial softmax over this CTA's 128 t-values -> one float4
// (m, den, num, 0) per (row, t-slice).
// ---------------------------------------------------------------------------
__global__ void __launch_bounds__(256, 2) gemm_dual(
    const __nv_bfloat16* __restrict__ A0, const __nv_bfloat16* __restrict__ A1,
    const __nv_bfloat16* __restrict__ B0, const __nv_bfloat16* __restrict__ B1,
    const __nv_bfloat16* __restrict__ C0, const __nv_bfloat16* __restrict__ C1,
    const float* __restrict__ qv, const float* __restrict__ y1,
    float4* __restrict__ part,
    int K, size_t sA, size_t sB)
{
    constexpr unsigned TA = 64 * 128;     // 8 KB
    constexpr unsigned TB = 128 * 128;    // 16 KB
    // single stage: Ah, Al, Nh, Nl, Qh, Ql = 80 KB

    extern __shared__ char smem[];
    const unsigned sbase = smem_u32(smem);

    const int tid = threadIdx.x;
    const int lid = tid & 31;
    const int wid = tid >> 5;
    const int wm = wid & 1;
    const int wn = wid >> 1;

    const size_t zb = blockIdx.z;
    const __nv_bfloat16* AP[2] = { A0 + zb * sA, A1 + zb * sA };
    const __nv_bfloat16* BP[4] = { B0 + zb * sB, B1 + zb * sB,
                                   C0 + zb * sB, C1 + zb * sB };
    const size_t rm0 = (size_t)blockIdx.y * 64;
    const size_t rn0 = (size_t)blockIdx.x * 128;
    const int NC = K >> 6;

    float c1[2][4][4] = {};
    float c2[2][4][4] = {};

    const int al_r  = lid & 15;
    const int al_k  = (lid >> 4) & 1;
    const int bl_r  = (lid & 7) + ((lid >> 4) << 3);
    const int bl_k  = (lid >> 3) & 1;

    auto load_stage = [&](int ck) {
        const int k0 = ck << 6;
        #pragma unroll
        for (int sp = 0; sp < 2; sp++) {
            #pragma unroll
            for (int i = 0; i < 2; i++) {
                int idx = i * 256 + tid;
                int row = idx >> 3, g = idx & 7;
                const __nv_bfloat16* gs = AP[sp] + (rm0 + row) * (size_t)K + k0 + g * 8;
                unsigned d = sbase + (unsigned)sp * TA + swz((unsigned)(row * 128 + g * 16));
                CP_ASYNC16(d, gs);
            }
        }
        #pragma unroll
        for (int t4 = 0; t4 < 4; t4++) {
            #pragma unroll
            for (int i = 0; i < 4; i++) {
                int idx = i * 256 + tid;
                int row = idx >> 3, g = idx & 7;
                const __nv_bfloat16* gs = BP[t4] + (rn0 + row) * (size_t)K + k0 + g * 8;
                unsigned d = sbase + 2 * TA + (unsigned)t4 * TB +
                             swz((unsigned)(row * 128 + g * 16));
                CP_ASYNC16(d, gs);
            }
        }
    };

    for (int ck = 0; ck < NC; ck++) {
        load_stage(ck);
        CP_COMMIT();
        CP_WAIT0();
        __syncthreads();

        const unsigned sb2 = sbase;
        #pragma unroll
        for (int ks = 0; ks < 4; ks++) {
            unsigned af[2][2][4];
            #pragma unroll
            for (int sp = 0; sp < 2; sp++)
                #pragma unroll
                for (int mt = 0; mt < 2; mt++) {
                    unsigned addr = sb2 + (unsigned)sp * TA +
                        swz((unsigned)((wm * 32 + mt * 16 + al_r) * 128 + ks * 32 + al_k * 16));
                    ldsm4(af[sp][mt], addr);
                }
            {
                unsigned bf[2][4][2];
                #pragma unroll
                for (int sp = 0; sp < 2; sp++)
                    #pragma unroll
                    for (int np = 0; np < 2; np++) {
                        unsigned r[4];
                        unsigned addr = sb2 + 2 * TA + (unsigned)sp * TB +
                            swz((unsigned)((wn * 32 + np * 16 + bl_r) * 128 + ks * 32 + bl_k * 16));
                        ldsm4(r, addr);
                        bf[sp][2 * np][0] = r[0]; bf[sp][2 * np][1] = r[1];
                        bf[sp][2 * np + 1][0] = r[2]; bf[sp][2 * np + 1][1] = r[3];
                    }
                #pragma unroll
                for (int tm = 0; tm < 3; tm++) {
                    const int i = (tm == 2) ? 1 : 0;
                    const int j = (tm == 1) ? 1 : 0;
                    #pragma unroll
                    for (int mt = 0; mt < 2; mt++)
                        #pragma unroll
                        for (int nt = 0; nt < 4; nt++)
                            mma_bf16(c1[mt][nt], af[i][mt], bf[j][nt]);
                }
            }
            {
                unsigned bf[2][4][2];
                #pragma unroll
                for (int sp = 0; sp < 2; sp++)
                    #pragma unroll
                    for (int np = 0; np < 2; np++) {
                        unsigned r[4];
                        unsigned addr = sb2 + 2 * TA + (unsigned)(2 + sp) * TB +
                            swz((unsigned)((wn * 32 + np * 16 + bl_r) * 128 + ks * 32 + bl_k * 16));
                        ldsm4(r, addr);
                        bf[sp][2 * np][0] = r[0]; bf[sp][2 * np][1] = r[1];
                        bf[sp][2 * np + 1][0] = r[2]; bf[sp][2 * np + 1][1] = r[3];
                    }
                #pragma unroll
                for (int tm = 0; tm < 3; tm++) {
                    const int i = (tm == 2) ? 1 : 0;
                    const int j = (tm == 1) ? 1 : 0;
                    #pragma unroll
                    for (int mt = 0; mt < 2; mt++)
                        #pragma unroll
                        for (int nt = 0; nt < 4; nt++)
                            mma_bf16(c2[mt][nt], af[i][mt], bf[j][nt]);
                }
            }
        }
        __syncthreads();
    }

    // ---- Fused split-softmax epilogue ----
    const int qr = lid >> 2;
    const int qc = (lid & 3) * 2;
    const size_t boff = zb * TT;
    const int tbase = (int)rn0 + wn * 32;

    float2 qvv[4], y1v[4];
    #pragma unroll
    for (int nt = 0; nt < 4; nt++) {
        int t0 = tbase + nt * 8 + qc;
        qvv[nt] = *reinterpret_cast<const float2*>(qv + boff + t0);
        y1v[nt] = *reinterpret_cast<const float2*>(y1 + boff + t0);
    }

    float* sp = reinterpret_cast<float*>(smem);   // [64 rows][4 wn][3] = 3 KB

    #pragma unroll
    for (int mt = 0; mt < 2; mt++) {
        #pragma unroll
        for (int half = 0; half < 2; half++) {
            float sv[8];
            float m = -1e30f;
            #pragma unroll
            for (int nt = 0; nt < 4; nt++) {
                sv[2 * nt]     = c1[mt][nt][2 * half]     + qvv[nt].x;
                sv[2 * nt + 1] = c1[mt][nt][2 * half + 1] + qvv[nt].y;
                m = fmaxf(m, fmaxf(sv[2 * nt], sv[2 * nt + 1]));
            }
            float den = 0.f, num = 0.f;
            #pragma unroll
            for (int nt = 0; nt < 4; nt++) {
                float e0 = __expf(sv[2 * nt] - m);
                float e1 = __expf(sv[2 * nt + 1] - m);
                den += e0 + e1;
                num = fmaf(e0, y1v[nt].x + c2[mt][nt][2 * half], num);
                num = fmaf(e1, y1v[nt].y + c2[mt][nt][2 * half + 1], num);
            }
            // merge across the 4 qc-lanes (lid^1, lid^2)
            #pragma unroll
            for (int o = 1; o <= 2; o <<= 1) {
                float mo = __shfl_xor_sync(0xffffffffu, m, o);
                float dn = __shfl_xor_sync(0xffffffffu, den, o);
                float no = __shfl_xor_sync(0xffffffffu, num, o);
                float mn = fmaxf(m, mo);
                float sa = __expf(m - mn), sb = __expf(mo - mn);
                den = den * sa + dn * sb;
                num = num * sa + no * sb;
                m = mn;
            }
            if ((lid & 3) == 0) {
                int lr = wm * 32 + mt * 16 + qr + half * 8;
                sp[(lr * 4 + wn) * 3 + 0] = m;
                sp[(lr * 4 + wn) * 3 + 1] = den;
                sp[(lr * 4 + wn) * 3 + 2] = num;
            }
        }
    }
    __syncthreads();
    if (tid < 64) {
        float m = -1e30f;
        #pragma unroll
        for (int w = 0; w < 4; w++) m = fmaxf(m, sp[(tid * 4 + w) * 3]);
        float den = 0.f, num = 0.f;
        #pragma unroll
        for (int w = 0; w < 4; w++) {
            float s = __expf(sp[(tid * 4 + w) * 3] - m);
            den = fmaf(sp[(tid * 4 + w) * 3 + 1], s, den);
            num = fmaf(sp[(tid * 4 + w) * 3 + 2], s, num);
        }
        size_t row = zb * RR + rm0 + tid;
        part[row * 4 + blockIdx.x] = make_float4(m, den, num, 0.f);
    }
}

// ---------------------------------------------------------------------------
// Finalize: merge 4 softmax partials per row; out = rd0 + num/den + bs
// ---------------------------------------------------------------------------
__global__ void __launch_bounds__(256) finalize_k(
    const float4* __restrict__ part, const float* __restrict__ rd0,
    const float* __restrict__ bs, float* __restrict__ out)
{
    int i = blockIdx.x * 256 + threadIdx.x;
    float4 p0 = part[(size_t)i * 4 + 0];
    float4 p1 = part[(size_t)i * 4 + 1];
    float4 p2 = part[(size_t)i * 4 + 2];
    float4 p3 = part[(size_t)i * 4 + 3];
    float m = fmaxf(fmaxf(p0.x, p1.x), fmaxf(p2.x, p3.x));
    float s0 = __expf(p0.x - m), s1 = __expf(p1.x - m);
    float s2 = __expf(p2.x - m), s3 = __expf(p3.x - m);
    float den = p0.y * s0 + p1.y * s1 + p2.y * s2 + p3.y * s3;
    float num = p0.z * s0 + p1.z * s1 + p2.z * s2 + p3.z * s3;
    out[i] = rd0[i] + num / den + bs[0];
}

// ---------------------------------------------------------------------------
// Merged weight split: blocks [0,512) handle Wr, [512,1024) handle Wq.
// ---------------------------------------------------------------------------
__global__ void __launch_bounds__(256) split2w_k(
    const float4* __restrict__ Wr, const float4* __restrict__ Wq,
    __nv_bfloat16* __restrict__ Wr_h, __nv_bfloat16* __restrict__ Wr_l,
    __nv_bfloat16* __restrict__ Wq_h, __nv_bfloat16* __restrict__ Wq_l)
{
    const int n4 = DD * HH / 4;
    const bool second = blockIdx.x >= 512;
    const float4* x = second ? Wq : Wr;
    __nv_bfloat16* h = second ? Wq_h : Wr_h;
    __nv_bfloat16* l = second ? Wq_l : Wr_l;
    int b0 = second ? (blockIdx.x - 512) : blockIdx.x;
    for (int i = b0 * 256 + threadIdx.x; i < n4; i += 512 * 256) {
        float4 v = x[i];
        float a[4] = {v.x, v.y, v.z, v.w};
        __nv_bfloat16 hh[4], ll[4];
        #pragma unroll
        for (int k = 0; k < 4; k++) {
            hh[k] = __float2bfloat16(a[k]);
            ll[k] = __float2bfloat16(a[k] - __bfloat162float(hh[k]));
        }
        __nv_bfloat162 p0, p1;
        p0.x = hh[0]; p0.y = hh[1]; p1.x = hh[2]; p1.y = hh[3];
        reinterpret_cast<__nv_bfloat162*>(h)[2 * i] = p0;
        reinterpret_cast<__nv_bfloat162*>(h)[2 * i + 1] = p1;
        p0.x = ll[0]; p0.y = ll[1]; p1.x = ll[2]; p1.y = ll[3];
        reinterpret_cast<__nv_bfloat162*>(l)[2 * i] = p0;
        reinterpret_cast<__nv_bfloat162*>(l)[2 * i + 1] = p1;
    }
}

// ---------------------------------------------------------------------------
// region prep: one CTA per (b,r) row. Writes rf_h/rf_l; computes rd0 = row.Ws0.
// ---------------------------------------------------------------------------
__global__ void __launch_bounds__(256) region_prep_k(
    const float* __restrict__ region, const float* __restrict__ Ws0,
    __nv_bfloat16* __restrict__ rf_h, __nv_bfloat16* __restrict__ rf_l,
    float* __restrict__ rd0)
{
    size_t row = blockIdx.x;
    int t = threadIdx.x;
    float4 a = *reinterpret_cast<const float4*>(region + row * DD + t * 4);
    float4 w = *reinterpret_cast<const float4*>(Ws0 + t * 4);

    __nv_bfloat162 h0, h1, l0, l1;
    h0.x = __float2bfloat16(a.x); h0.y = __float2bfloat16(a.y);
    h1.x = __float2bfloat16(a.z); h1.y = __float2bfloat16(a.w);
    l0.x = __float2bfloat16(a.x - __bfloat162float(h0.x));
    l0.y = __float2bfloat16(a.y - __bfloat162float(h0.y));
    l1.x = __float2bfloat16(a.z - __bfloat162float(h1.x));
    l1.y = __float2bfloat16(a.w - __bfloat162float(h1.y));
    reinterpret_cast<__nv_bfloat162*>(rf_h + row * DD)[2 * t] = h0;
    reinterpret_cast<__nv_bfloat162*>(rf_h + row * DD)[2 * t + 1] = h1;
    reinterpret_cast<__nv_bfloat162*>(rf_l + row * DD)[2 * t] = l0;
    reinterpret_cast<__nv_bfloat162*>(rf_l + row * DD)[2 * t + 1] = l1;

    float p = a.x * w.x + a.y * w.y + a.z * w.z + a.w * w.w;
    __shared__ float red[8];
    #pragma unroll
    for (int o = 16; o; o >>= 1) p += __shfl_xor_sync(0xffffffffu, p, o);
    if ((t & 31) == 0) red[t >> 5] = p;
    __syncthreads();
    if (t == 0) {
        float s = 0.f;
        #pragma unroll
        for (int i = 0; i < 8; i++) s += red[i];
        rd0[row] = s;
    }
}

// ---------------------------------------------------------------------------
// query prep: one CTA per (b,t) row. Writes qe_h/l and qe2_h/l (= qe*Ws2);
// computes qv = row.v and y1 = row.Ws1.
// ---------------------------------------------------------------------------
__global__ void __launch_bounds__(256) query_prep_k(
    const float* __restrict__ query, const float* __restrict__ v,
    const float* __restrict__ Ws1, const float* __restrict__ Ws2,
    __nv_bfloat16* __restrict__ qe_h, __nv_bfloat16* __restrict__ qe_l,
    __nv_bfloat16* __restrict__ qe2_h, __nv_bfloat16* __restrict__ qe2_l,
    float* __restrict__ qv, float* __restrict__ y1)
{
    size_t row = blockIdx.x;
    int t = threadIdx.x;
    float4 a = *reinterpret_cast<const float4*>(query + row * DD + t * 4);
    float4 vv = *reinterpret_cast<const float4*>(v + t * 4);
    float4 w1 = *reinterpret_cast<const float4*>(Ws1 + t * 4);
    float4 w2 = *reinterpret_cast<const float4*>(Ws2 + t * 4);

    __nv_bfloat162 h0, h1, l0, l1;
    h0.x = __float2bfloat16(a.x); h0.y = __float2bfloat16(a.y);
    h1.x = __float2bfloat16(a.z); h1.y = __float2bfloat16(a.w);
    l0.x = __float2bfloat16(a.x - __bfloat162float(h0.x));
    l0.y = __float2bfloat16(a.y - __bfloat162float(h0.y));
    l1.x = __float2bfloat16(a.z - __bfloat162float(h1.x));
    l1.y = __float2bfloat16(a.w - __bfloat162float(h1.y));
    reinterpret_cast<__nv_bfloat162*>(qe_h + row * DD)[2 * t] = h0;
    reinterpret_cast<__nv_bfloat162*>(qe_h + row * DD)[2 * t + 1] = h1;
    reinterpret_cast<__nv_bfloat162*>(qe_l + row * DD)[2 * t] = l0;
    reinterpret_cast<__nv_bfloat162*>(qe_l + row * DD)[2 * t + 1] = l1;

    float b0 = a.x * w2.x, b1 = a.y * w2.y, b2 = a.z * w2.z, b3 = a.w * w2.w;
    h0.x = __float2bfloat16(b0); h0.y = __float2bfloat16(b1);
    h1.x = __float2bfloat16(b2); h1.y = __float2bfloat16(b3);
    l0.x = __float2bfloat16(b0 - __bfloat162float(h0.x));
    l0.y = __float2bfloat16(b1 - __bfloat162float(h0.y));
    l1.x = __float2bfloat16(b2 - __bfloat162float(h1.x));
    l1.y = __float2bfloat16(b3 - __bfloat162float(h1.y));
    reinterpret_cast<__nv_bfloat162*>(qe2_h + row * DD)[2 * t] = h0;
    reinterpret_cast<__nv_bfloat162*>(qe2_h + row * DD)[2 * t + 1] = h1;
    reinterpret_cast<__nv_bfloat162*>(qe2_l + row * DD)[2 * t] = l0;
    reinterpret_cast<__nv_bfloat162*>(qe2_l + row * DD)[2 * t + 1] = l1;

    float p = a.x * vv.x + a.y * vv.y + a.z * vv.z + a.w * vv.w;
    float q = a.x * w1.x + a.y * w1.y + a.z * w1.z + a.w * w1.w;
    __shared__ float red[16];
    #pragma unroll
    for (int o = 16; o; o >>= 1) {
        p += __shfl_xor_sync(0xffffffffu, p, o);
        q += __shfl_xor_sync(0xffffffffu, q, o);
    }
    if ((t & 31) == 0) { red[t >> 5] = p; red[8 + (t >> 5)] = q; }
    __syncthreads();
    if (t == 0) {
        float s = 0.f, s2 = 0.f;
        #pragma unroll
        for (int i = 0; i < 8; i++) { s += red[i]; s2 += red[8 + i]; }
        qv[row] = s;
        y1[row] = s2;
    }
}

// ---------------------------------------------------------------------------
// v[d] = sum_h Wq[d,h] * br[h]
// ---------------------------------------------------------------------------
__global__ void __launch_bounds__(256) matvec_k(
    const float* __restrict__ W, const float* __restrict__ b,
    float* __restrict__ v, int H)
{
    const float* row = W + (size_t)blockIdx.x * H;
    int t = threadIdx.x;
    float p = 0.f;
    for (int h = t * 4; h < H; h += 1024) {
        float4 wv = *reinterpret_cast<const float4*>(row + h);
        float4 bv = *reinterpret_cast<const float4*>(b + h);
        p = fmaf(wv.x, bv.x, p); p = fmaf(wv.y, bv.y, p);
        p = fmaf(wv.z, bv.z, p); p = fmaf(wv.w, bv.w, p);
    }
    __shared__ float red[8];
    #pragma unroll
    for (int o = 16; o; o >>= 1) p += __shfl_xor_sync(0xffffffffu, p, o);
    if ((t & 31) == 0) red[t >> 5] = p;
    __syncthreads();
    if (t == 0) {
        float s = 0.f;
        #pragma unroll
        for (int i = 0; i < 8; i++) s += red[i];
        v[blockIdx.x] = s;
    }
}

// ---------------------------------------------------------------------------
extern "C" void kernel_launch(void* const* d_in, const int* in_sizes, int n_in,
                              void* d_out, int out_size)
{
    const float* region = (const float*)d_in[0];
    const float* query  = (const float*)d_in[1];
    const float* Wr     = (const float*)d_in[2];
    const float* br     = (const float*)d_in[3];
    const float* Wq     = (const float*)d_in[4];
    const float* bq     = (const float*)d_in[5];
    const float* Ws     = (const float*)d_in[6];
    const float* bs     = (const float*)d_in[7];
    float* out = (float*)d_out;
    (void)bq;  // softmax-invariant terms drop out

    __nv_bfloat16 *Wr_h, *Wr_l, *Wq_h, *Wq_l, *M2_h, *M2_l;
    __nv_bfloat16 *rf_h, *rf_l, *qe_h, *qe_l, *qe2_h, *qe2_l, *Nt_h, *Nt_l;
    float4 *partb;
    float *v, *qv, *y1, *rd0;
    cudaGetSymbolAddress((void**)&Wr_h, g_Wr_h);
    cudaGetSymbolAddress((void**)&Wr_l, g_Wr_l);
    cudaGetSymbolAddress((void**)&Wq_h, g_Wq_h);
    cudaGetSymbolAddress((void**)&Wq_l, g_Wq_l);
    cudaGetSymbolAddress((void**)&M2_h, g_M2_h);
    cudaGetSymbolAddress((void**)&M2_l, g_M2_l);
    cudaGetSymbolAddress((void**)&rf_h, g_rf_h);
    cudaGetSymbolAddress((void**)&rf_l, g_rf_l);
    cudaGetSymbolAddress((void**)&qe_h, g_qe_h);
    cudaGetSymbolAddress((void**)&qe_l, g_qe_l);
    cudaGetSymbolAddress((void**)&qe2_h, g_qe2_h);
    cudaGetSymbolAddress((void**)&qe2_l, g_qe2_l);
    cudaGetSymbolAddress((void**)&Nt_h, g_Nt_h);
    cudaGetSymbolAddress((void**)&Nt_l, g_Nt_l);
    cudaGetSymbolAddress((void**)&partb, g_part);
    cudaGetSymbolAddress((void**)&v, g_v);
    cudaGetSymbolAddress((void**)&qv, g_qv);
    cudaGetSymbolAddress((void**)&y1, g_y1);
    cudaGetSymbolAddress((void**)&rd0, g_rd0);

    const int SMEM1 = 2 * (2 * 8192 + 2 * 16384);       // 98304 (2-stage, 48KB) -> 2 CTAs/SM
    const int SMEMD = 2 * 8192 + 4 * 16384;             // 81920 (1-stage, 80KB) -> 2 CTAs/SM
    cudaFuncSetAttribute(gemm_mma1, cudaFuncAttributeMaxDynamicSharedMemorySize, SMEM1);
    cudaFuncSetAttribute(gemm_dual, cudaFuncAttributeMaxDynamicSharedMemorySize, SMEMD);

    // 1) merged weight splits + bias matvec
    split2w_k<<<1024, 256>>>((const float4*)Wr, (const float4*)Wq,
                             Wr_h, Wr_l, Wq_h, Wq_l);
    matvec_k<<<DD, 256>>>(Wq, br, v, HH);
    // 2) fused activation prep (single pass over region and query)
    region_prep_k<<<BB * RR, 256>>>(region, Ws, rf_h, rf_l, rd0);
    query_prep_k<<<BB * TT, 256>>>(query, v, Ws + DD, Ws + 2 * DD,
                                   qe_h, qe_l, qe2_h, qe2_l, qv, y1);
    // 3) M2[d,e] = sum_h Wr[d,h] Wq[e,h]  (e contiguous), split output
    gemm_mma1<<<dim3(DD / 128, DD / 64, 1), 256, SMEM1>>>(
        Wr_h, Wr_l, Wq_h, Wq_l, M2_h, M2_l, HH, 0, 0, 0, DD);
    // 4) Nt[b][t,d] = sum_e qe[b,t,e] M2[d,e]  (d contiguous), split output
    gemm_mma1<<<dim3(DD / 128, TT / 64, BB), 256, SMEM1>>>(
        qe_h, qe_l, M2_h, M2_l, Nt_h, Nt_l,
        DD, (size_t)TT * DD, 0, (size_t)TT * DD, DD);
    // 5) dual GEMM (1-stage, 2 CTAs/SM) with fused split-softmax -> partials
    gemm_dual<<<dim3(TT / 128, RR / 64, BB), 256, SMEMD>>>(
        rf_h, rf_l, Nt_h, Nt_l, qe2_h, qe2_l, qv, y1, partb,
        DD, (size_t)RR * DD, (size_t)TT * DD);
    // 6) finalize: merge partials -> out
    finalize_k<<<BB * RR / 256, 256>>>(partb, rd0, bs, out);
}

// round 17
// speedup vs baseline: 1.1934x; 1.0307x over previous
#include <cuda_runtime.h>
#include <cuda_bf16.h>

#define BB 16
#define RR 1024
#define TT 512
#define DD 1024
#define HH 1024

// ---------------------------------------------------------------------------
// Scratch (device globals — allocations are forbidden)
// ---------------------------------------------------------------------------
__device__ __nv_bfloat16 g_Wr_h[DD * HH], g_Wr_l[DD * HH];
__device__ __nv_bfloat16 g_Wq_h[DD * HH], g_Wq_l[DD * HH];
__device__ __nv_bfloat16 g_M2_h[DD * DD], g_M2_l[DD * DD];       // M2[d,e] = sum_h Wr[d,h]Wq[e,h]
__device__ __nv_bfloat16 g_rf_h[(size_t)BB * RR * DD], g_rf_l[(size_t)BB * RR * DD];
__device__ __nv_bfloat16 g_qe_h[(size_t)BB * TT * DD], g_qe_l[(size_t)BB * TT * DD];
__device__ __nv_bfloat16 g_qe2_h[(size_t)BB * TT * DD], g_qe2_l[(size_t)BB * TT * DD]; // qe*Ws2
__device__ __nv_bfloat16 g_Nt_h[(size_t)BB * TT * DD], g_Nt_l[(size_t)BB * TT * DD];   // Nt[b][t,d]
__device__ float4        g_part[(size_t)BB * RR * 4];   // (m, den, num, pad) per t-slice
__device__ float         g_v[DD];
__device__ float         g_qv[BB * TT];
__device__ float         g_y1[BB * TT];
__device__ float         g_rd0[BB * RR];

// ---------------------------------------------------------------------------
// PTX helpers (sm_80-level features only: ldmatrix, cp.async, mma.sync)
// ---------------------------------------------------------------------------
__device__ __forceinline__ unsigned smem_u32(const void* p) {
    unsigned a;
    asm("{ .reg .u64 t; cvta.to.shared.u64 t, %1; cvt.u32.u64 %0, t; }" : "=r"(a) : "l"(p));
    return a;
}

#define CP_ASYNC16(dst, src) \
    asm volatile("cp.async.cg.shared.global [%0], [%1], 16;" :: "r"(dst), "l"(src))
#define CP_COMMIT() asm volatile("cp.async.commit_group;" ::: "memory")
#define CP_WAIT0()  asm volatile("cp.async.wait_group 0;" ::: "memory")
#define CP_WAIT1()  asm volatile("cp.async.wait_group 1;" ::: "memory")

__device__ __forceinline__ void ldsm4(unsigned* r, unsigned addr) {
    asm volatile("ldmatrix.sync.aligned.m8n8.x4.shared.b16 {%0,%1,%2,%3}, [%4];"
                 : "=r"(r[0]), "=r"(r[1]), "=r"(r[2]), "=r"(r[3]) : "r"(addr));
}

__device__ __forceinline__ void mma_bf16(float* c, const unsigned* a, const unsigned* b) {
    asm volatile(
        "mma.sync.aligned.m16n8k16.row.col.f32.bf16.bf16.f32 "
        "{%0,%1,%2,%3}, {%4,%5,%6,%7}, {%8,%9}, {%0,%1,%2,%3};"
        : "+f"(c[0]), "+f"(c[1]), "+f"(c[2]), "+f"(c[3])
        : "r"(a[0]), "r"(a[1]), "r"(a[2]), "r"(a[3]), "r"(b[0]), "r"(b[1]));
}

__device__ __forceinline__ unsigned swz(unsigned off) {
    return off ^ ((off >> 3) & 0x70);
}

// ---------------------------------------------------------------------------
// Split-bf16 GEMM, CTA tile 64x128 (8 warps = 2M x 4N, warp tile 32x32).
// 3 terms: hh + hl + lh. K chunks of 64 bf16 (SW128), 2-stage cp.async,
// 2 CTAs/SM (cross-CTA latency hiding). Split hi/lo bf16 output (M2, Nt).
// ---------------------------------------------------------------------------
__global__ void __launch_bounds__(256, 2) gemm_mma1(
    const __nv_bfloat16* __restrict__ A0, const __nv_bfloat16* __restrict__ A1,
    const __nv_bfloat16* __restrict__ B0, const __nv_bfloat16* __restrict__ B1,
    __nv_bfloat16* __restrict__ Ch, __nv_bfloat16* __restrict__ Cl,
    int K, size_t sA, size_t sB, size_t sC, int ldc)
{
    constexpr unsigned TA = 64 * 128;     // 8 KB per A split tile
    constexpr unsigned TB = 128 * 128;    // 16 KB per B split tile
    constexpr unsigned STAGE = 2 * TA + 2 * TB;   // 48 KB

    extern __shared__ char smem[];
    const unsigned sbase = smem_u32(smem);

    const int tid = threadIdx.x;
    const int lid = tid & 31;
    const int wid = tid >> 5;
    const int wm = wid & 1;
    const int wn = wid >> 1;

    const size_t zb = blockIdx.z;
    const __nv_bfloat16* AP[2] = { A0 + zb * sA, A1 + zb * sA };
    const __nv_bfloat16* BP[2] = { B0 + zb * sB, B1 + zb * sB };
    const size_t rm0 = (size_t)blockIdx.y * 64;
    const size_t rn0 = (size_t)blockIdx.x * 128;
    const int NC = K >> 6;

    float c[2][4][4] = {};

    const int al_r  = lid & 15;
    const int al_k  = (lid >> 4) & 1;
    const int bl_r  = (lid & 7) + ((lid >> 4) << 3);
    const int bl_k  = (lid >> 3) & 1;

    auto load_stage = [&](int st, int ck) {
        const unsigned sdst = sbase + (unsigned)st * STAGE;
        const int k0 = ck << 6;
        #pragma unroll
        for (int sp = 0; sp < 2; sp++) {
            #pragma unroll
            for (int i = 0; i < 2; i++) {
                int idx = i * 256 + tid;
                int row = idx >> 3, g = idx & 7;
                const __nv_bfloat16* gs = AP[sp] + (rm0 + row) * (size_t)K + k0 + g * 8;
                unsigned d = sdst + (unsigned)sp * TA + swz((unsigned)(row * 128 + g * 16));
                CP_ASYNC16(d, gs);
            }
        }
        #pragma unroll
        for (int sp = 0; sp < 2; sp++) {
            #pragma unroll
            for (int i = 0; i < 4; i++) {
                int idx = i * 256 + tid;
                int row = idx >> 3, g = idx & 7;
                const __nv_bfloat16* gs = BP[sp] + (rn0 + row) * (size_t)K + k0 + g * 8;
                unsigned d = sdst + 2 * TA + (unsigned)sp * TB +
                             swz((unsigned)(row * 128 + g * 16));
                CP_ASYNC16(d, gs);
            }
        }
    };

    load_stage(0, 0); CP_COMMIT();

    for (int ck = 0; ck < NC; ck++) {
        if (ck + 1 < NC) {
            load_stage((ck + 1) & 1, ck + 1);
            CP_COMMIT();
            CP_WAIT1();
        } else {
            CP_WAIT0();
        }
        __syncthreads();

        const unsigned sb2 = sbase + (unsigned)(ck & 1) * STAGE;
        #pragma unroll
        for (int ks = 0; ks < 4; ks++) {
            unsigned af[2][2][4];
            unsigned bf[2][4][2];
            #pragma unroll
            for (int sp = 0; sp < 2; sp++) {
                #pragma unroll
                for (int mt = 0; mt < 2; mt++) {
                    unsigned addr = sb2 + (unsigned)sp * TA +
                        swz((unsigned)((wm * 32 + mt * 16 + al_r) * 128 + ks * 32 + al_k * 16));
                    ldsm4(af[sp][mt], addr);
                }
                #pragma unroll
                for (int np = 0; np < 2; np++) {
                    unsigned r[4];
                    unsigned addr = sb2 + 2 * TA + (unsigned)sp * TB +
                        swz((unsigned)((wn * 32 + np * 16 + bl_r) * 128 + ks * 32 + bl_k * 16));
                    ldsm4(r, addr);
                    bf[sp][2 * np][0] = r[0]; bf[sp][2 * np][1] = r[1];
                    bf[sp][2 * np + 1][0] = r[2]; bf[sp][2 * np + 1][1] = r[3];
                }
            }
            #pragma unroll
            for (int tm = 0; tm < 3; tm++) {
                const int i = (tm == 2) ? 1 : 0;
                const int j = (tm == 1) ? 1 : 0;
                #pragma unroll
                for (int mt = 0; mt < 2; mt++)
                    #pragma unroll
                    for (int nt = 0; nt < 4; nt++)
                        mma_bf16(c[mt][nt], af[i][mt], bf[j][nt]);
            }
        }
        __syncthreads();
    }

    const int qr = lid >> 2;
    const int qc = (lid & 3) * 2;
    #pragma unroll
    for (int mt = 0; mt < 2; mt++) {
        #pragma unroll
        for (int nt = 0; nt < 4; nt++) {
            size_t gr = rm0 + wm * 32 + mt * 16 + qr;
            int gc = (int)rn0 + wn * 32 + nt * 8 + qc;
            #pragma unroll
            for (int half = 0; half < 2; half++) {
                float v0 = c[mt][nt][2 * half + 0];
                float v1 = c[mt][nt][2 * half + 1];
                size_t o = zb * sC + (gr + half * 8) * (size_t)ldc + gc;
                __nv_bfloat162 hv, lv;
                hv.x = __float2bfloat16(v0);
                hv.y = __float2bfloat16(v1);
                lv.x = __float2bfloat16(v0 - __bfloat162float(hv.x));
                lv.y = __float2bfloat16(v1 - __bfloat162float(hv.y));
                *reinterpret_cast<__nv_bfloat162*>(Ch + o) = hv;
                *reinterpret_cast<__nv_bfloat162*>(Cl + o) = lv;
            }
        }
    }
}

// ---------------------------------------------------------------------------
// Dual-B GEMM with fused split-softmax epilogue. CTA tile 64x128,
// single-stage smem (80 KB) at 2 CTAs/SM, with SPLIT-WAIT: per chunk the
// A+Nt tiles are one cp.async group and the qe2 tiles another; the c1 pass
// (A x Nt) runs while the qe2 group is still in flight.
// ---------------------------------------------------------------------------
__global__ void __launch_bounds__(256, 2) gemm_dual(
    const __nv_bfloat16* __restrict__ A0, const __nv_bfloat16* __restrict__ A1,
    const __nv_bfloat16* __restrict__ B0, const __nv_bfloat16* __restrict__ B1,
    const __nv_bfloat16* __restrict__ C0, const __nv_bfloat16* __restrict__ C1,
    const float* __restrict__ qv, const float* __restrict__ y1,
    float4* __restrict__ part,
    int K, size_t sA, size_t sB)
{
    constexpr unsigned TA = 64 * 128;     // 8 KB
    constexpr unsigned TB = 128 * 128;    // 16 KB
    // single stage: Ah, Al, Nh, Nl, Qh, Ql = 80 KB

    extern __shared__ char smem[];
    const unsigned sbase = smem_u32(smem);

    const int tid = threadIdx.x;
    const int lid = tid & 31;
    const int wid = tid >> 5;
    const int wm = wid & 1;
    const int wn = wid >> 1;

    const size_t zb = blockIdx.z;
    const __nv_bfloat16* AP[2] = { A0 + zb * sA, A1 + zb * sA };
    const __nv_bfloat16* BP[4] = { B0 + zb * sB, B1 + zb * sB,
                                   C0 + zb * sB, C1 + zb * sB };
    const size_t rm0 = (size_t)blockIdx.y * 64;
    const size_t rn0 = (size_t)blockIdx.x * 128;
    const int NC = K >> 6;

    float c1[2][4][4] = {};
    float c2[2][4][4] = {};

    const int al_r  = lid & 15;
    const int al_k  = (lid >> 4) & 1;
    const int bl_r  = (lid & 7) + ((lid >> 4) << 3);
    const int bl_k  = (lid >> 3) & 1;

    for (int ck = 0; ck < NC; ck++) {
        const int k0 = ck << 6;
        // group 1: A tiles + Nt tiles (48 KB)
        #pragma unroll
        for (int sp = 0; sp < 2; sp++) {
            #pragma unroll
            for (int i = 0; i < 2; i++) {
                int idx = i * 256 + tid;
                int row = idx >> 3, g = idx & 7;
                const __nv_bfloat16* gs = AP[sp] + (rm0 + row) * (size_t)K + k0 + g * 8;
                unsigned d = sbase + (unsigned)sp * TA + swz((unsigned)(row * 128 + g * 16));
                CP_ASYNC16(d, gs);
            }
        }
        #pragma unroll
        for (int sp = 0; sp < 2; sp++) {
            #pragma unroll
            for (int i = 0; i < 4; i++) {
                int idx = i * 256 + tid;
                int row = idx >> 3, g = idx & 7;
                const __nv_bfloat16* gs = BP[sp] + (rn0 + row) * (size_t)K + k0 + g * 8;
                unsigned d = sbase + 2 * TA + (unsigned)sp * TB +
                             swz((unsigned)(row * 128 + g * 16));
                CP_ASYNC16(d, gs);
            }
        }
        CP_COMMIT();
        // group 2: qe2 tiles (32 KB)
        #pragma unroll
        for (int sp = 0; sp < 2; sp++) {
            #pragma unroll
            for (int i = 0; i < 4; i++) {
                int idx = i * 256 + tid;
                int row = idx >> 3, g = idx & 7;
                const __nv_bfloat16* gs = BP[2 + sp] + (rn0 + row) * (size_t)K + k0 + g * 8;
                unsigned d = sbase + 2 * TA + (unsigned)(2 + sp) * TB +
                             swz((unsigned)(row * 128 + g * 16));
                CP_ASYNC16(d, gs);
            }
        }
        CP_COMMIT();

        // wait for A+Nt only; qe2 still in flight
        CP_WAIT1();
        __syncthreads();

        // c1 pass: rf x Nt
        #pragma unroll
        for (int ks = 0; ks < 4; ks++) {
            unsigned af[2][2][4];
            #pragma unroll
            for (int sp = 0; sp < 2; sp++)
                #pragma unroll
                for (int mt = 0; mt < 2; mt++) {
                    unsigned addr = sbase + (unsigned)sp * TA +
                        swz((unsigned)((wm * 32 + mt * 16 + al_r) * 128 + ks * 32 + al_k * 16));
                    ldsm4(af[sp][mt], addr);
                }
            unsigned bf[2][4][2];
            #pragma unroll
            for (int sp = 0; sp < 2; sp++)
                #pragma unroll
                for (int np = 0; np < 2; np++) {
                    unsigned r[4];
                    unsigned addr = sbase + 2 * TA + (unsigned)sp * TB +
                        swz((unsigned)((wn * 32 + np * 16 + bl_r) * 128 + ks * 32 + bl_k * 16));
                    ldsm4(r, addr);
                    bf[sp][2 * np][0] = r[0]; bf[sp][2 * np][1] = r[1];
                    bf[sp][2 * np + 1][0] = r[2]; bf[sp][2 * np + 1][1] = r[3];
                }
            #pragma unroll
            for (int tm = 0; tm < 3; tm++) {
                const int i = (tm == 2) ? 1 : 0;
                const int j = (tm == 1) ? 1 : 0;
                #pragma unroll
                for (int mt = 0; mt < 2; mt++)
                    #pragma unroll
                    for (int nt = 0; nt < 4; nt++)
                        mma_bf16(c1[mt][nt], af[i][mt], bf[j][nt]);
            }
        }

        // wait for qe2
        CP_WAIT0();
        __syncthreads();

        // c2 pass: rf x qe2
        #pragma unroll
        for (int ks = 0; ks < 4; ks++) {
            unsigned af[2][2][4];
            #pragma unroll
            for (int sp = 0; sp < 2; sp++)
                #pragma unroll
                for (int mt = 0; mt < 2; mt++) {
                    unsigned addr = sbase + (unsigned)sp * TA +
                        swz((unsigned)((wm * 32 + mt * 16 + al_r) * 128 + ks * 32 + al_k * 16));
                    ldsm4(af[sp][mt], addr);
                }
            unsigned bf[2][4][2];
            #pragma unroll
            for (int sp = 0; sp < 2; sp++)
                #pragma unroll
                for (int np = 0; np < 2; np++) {
                    unsigned r[4];
                    unsigned addr = sbase + 2 * TA + (unsigned)(2 + sp) * TB +
                        swz((unsigned)((wn * 32 + np * 16 + bl_r) * 128 + ks * 32 + bl_k * 16));
                    ldsm4(r, addr);
                    bf[sp][2 * np][0] = r[0]; bf[sp][2 * np][1] = r[1];
                    bf[sp][2 * np + 1][0] = r[2]; bf[sp][2 * np + 1][1] = r[3];
                }
            #pragma unroll
            for (int tm = 0; tm < 3; tm++) {
                const int i = (tm == 2) ? 1 : 0;
                const int j = (tm == 1) ? 1 : 0;
                #pragma unroll
                for (int mt = 0; mt < 2; mt++)
                    #pragma unroll
                    for (int nt = 0; nt < 4; nt++)
                        mma_bf16(c2[mt][nt], af[i][mt], bf[j][nt]);
            }
        }
        __syncthreads();
    }

    // ---- Fused split-softmax epilogue ----
    const int qr = lid >> 2;
    const int qc = (lid & 3) * 2;
    const size_t boff = zb * TT;
    const int tbase = (int)rn0 + wn * 32;

    float2 qvv[4], y1v[4];
    #pragma unroll
    for (int nt = 0; nt < 4; nt++) {
        int t0 = tbase + nt * 8 + qc;
        qvv[nt] = *reinterpret_cast<const float2*>(qv + boff + t0);
        y1v[nt] = *reinterpret_cast<const float2*>(y1 + boff + t0);
    }

    float* sp = reinterpret_cast<float*>(smem);   // [64 rows][4 wn][3] = 3 KB

    #pragma unroll
    for (int mt = 0; mt < 2; mt++) {
        #pragma unroll
        for (int half = 0; half < 2; half++) {
            float sv[8];
            float m = -1e30f;
            #pragma unroll
            for (int nt = 0; nt < 4; nt++) {
                sv[2 * nt]     = c1[mt][nt][2 * half]     + qvv[nt].x;
                sv[2 * nt + 1] = c1[mt][nt][2 * half + 1] + qvv[nt].y;
                m = fmaxf(m, fmaxf(sv[2 * nt], sv[2 * nt + 1]));
            }
            float den = 0.f, num = 0.f;
            #pragma unroll
            for (int nt = 0; nt < 4; nt++) {
                float e0 = __expf(sv[2 * nt] - m);
                float e1 = __expf(sv[2 * nt + 1] - m);
                den += e0 + e1;
                num = fmaf(e0, y1v[nt].x + c2[mt][nt][2 * half], num);
                num = fmaf(e1, y1v[nt].y + c2[mt][nt][2 * half + 1], num);
            }
            #pragma unroll
            for (int o = 1; o <= 2; o <<= 1) {
                float mo = __shfl_xor_sync(0xffffffffu, m, o);
                float dn = __shfl_xor_sync(0xffffffffu, den, o);
                float no = __shfl_xor_sync(0xffffffffu, num, o);
                float mn = fmaxf(m, mo);
                float sa = __expf(m - mn), sb = __expf(mo - mn);
                den = den * sa + dn * sb;
                num = num * sa + no * sb;
                m = mn;
            }
            if ((lid & 3) == 0) {
                int lr = wm * 32 + mt * 16 + qr + half * 8;
                sp[(lr * 4 + wn) * 3 + 0] = m;
                sp[(lr * 4 + wn) * 3 + 1] = den;
                sp[(lr * 4 + wn) * 3 + 2] = num;
            }
        }
    }
    __syncthreads();
    if (tid < 64) {
        float m = -1e30f;
        #pragma unroll
        for (int w = 0; w < 4; w++) m = fmaxf(m, sp[(tid * 4 + w) * 3]);
        float den = 0.f, num = 0.f;
        #pragma unroll
        for (int w = 0; w < 4; w++) {
            float s = __expf(sp[(tid * 4 + w) * 3] - m);
            den = fmaf(sp[(tid * 4 + w) * 3 + 1], s, den);
            num = fmaf(sp[(tid * 4 + w) * 3 + 2], s, num);
        }
        size_t row = zb * RR + rm0 + tid;
        part[row * 4 + blockIdx.x] = make_float4(m, den, num, 0.f);
    }
}

// ---------------------------------------------------------------------------
// Finalize: merge 4 softmax partials per row; out = rd0 + num/den + bs
// ---------------------------------------------------------------------------
__global__ void __launch_bounds__(256) finalize_k(
    const float4* __restrict__ part, const float* __restrict__ rd0,
    const float* __restrict__ bs, float* __restrict__ out)
{
    int i = blockIdx.x * 256 + threadIdx.x;
    float4 p0 = part[(size_t)i * 4 + 0];
    float4 p1 = part[(size_t)i * 4 + 1];
    float4 p2 = part[(size_t)i * 4 + 2];
    float4 p3 = part[(size_t)i * 4 + 3];
    float m = fmaxf(fmaxf(p0.x, p1.x), fmaxf(p2.x, p3.x));
    float s0 = __expf(p0.x - m), s1 = __expf(p1.x - m);
    float s2 = __expf(p2.x - m), s3 = __expf(p3.x - m);
    float den = p0.y * s0 + p1.y * s1 + p2.y * s2 + p3.y * s3;
    float num = p0.z * s0 + p1.z * s1 + p2.z * s2 + p3.z * s3;
    out[i] = rd0[i] + num / den + bs[0];
}

// ---------------------------------------------------------------------------
// Merged weight split: blocks [0,512) handle Wr, [512,1024) handle Wq.
// ---------------------------------------------------------------------------
__global__ void __launch_bounds__(256) split2w_k(
    const float4* __restrict__ Wr, const float4* __restrict__ Wq,
    __nv_bfloat16* __restrict__ Wr_h, __nv_bfloat16* __restrict__ Wr_l,
    __nv_bfloat16* __restrict__ Wq_h, __nv_bfloat16* __restrict__ Wq_l)
{
    const int n4 = DD * HH / 4;
    const bool second = blockIdx.x >= 512;
    const float4* x = second ? Wq : Wr;
    __nv_bfloat16* h = second ? Wq_h : Wr_h;
    __nv_bfloat16* l = second ? Wq_l : Wr_l;
    int b0 = second ? (blockIdx.x - 512) : blockIdx.x;
    for (int i = b0 * 256 + threadIdx.x; i < n4; i += 512 * 256) {
        float4 v = x[i];
        float a[4] = {v.x, v.y, v.z, v.w};
        __nv_bfloat16 hh[4], ll[4];
        #pragma unroll
        for (int k = 0; k < 4; k++) {
            hh[k] = __float2bfloat16(a[k]);
            ll[k] = __float2bfloat16(a[k] - __bfloat162float(hh[k]));
        }
        __nv_bfloat162 p0, p1;
        p0.x = hh[0]; p0.y = hh[1]; p1.x = hh[2]; p1.y = hh[3];
        reinterpret_cast<__nv_bfloat162*>(h)[2 * i] = p0;
        reinterpret_cast<__nv_bfloat162*>(h)[2 * i + 1] = p1;
        p0.x = ll[0]; p0.y = ll[1]; p1.x = ll[2]; p1.y = ll[3];
        reinterpret_cast<__nv_bfloat162*>(l)[2 * i] = p0;
        reinterpret_cast<__nv_bfloat162*>(l)[2 * i + 1] = p1;
    }
}

// ---------------------------------------------------------------------------
// Merged activation prep: blocks [0, B*R) = region rows; [B*R, B*R+B*T) =
// query rows. Region path: writes rf_h/l, rd0 = row.Ws0. Query path: writes
// qe_h/l, qe2_h/l (= qe*Ws2), qv = row.v, y1 = row.Ws1.
// ---------------------------------------------------------------------------
__global__ void __launch_bounds__(256) prep_k(
    const float* __restrict__ region, const float* __restrict__ query,
    const float* __restrict__ v, const float* __restrict__ Ws,
    __nv_bfloat16* __restrict__ rf_h, __nv_bfloat16* __restrict__ rf_l,
    __nv_bfloat16* __restrict__ qe_h, __nv_bfloat16* __restrict__ qe_l,
    __nv_bfloat16* __restrict__ qe2_h, __nv_bfloat16* __restrict__ qe2_l,
    float* __restrict__ rd0, float* __restrict__ qv, float* __restrict__ y1)
{
    int t = threadIdx.x;
    __shared__ float red[16];

    if (blockIdx.x < BB * RR) {
        size_t row = blockIdx.x;
        float4 a = *reinterpret_cast<const float4*>(region + row * DD + t * 4);
        float4 w = *reinterpret_cast<const float4*>(Ws + t * 4);

        __nv_bfloat162 h0, h1, l0, l1;
        h0.x = __float2bfloat16(a.x); h0.y = __float2bfloat16(a.y);
        h1.x = __float2bfloat16(a.z); h1.y = __float2bfloat16(a.w);
        l0.x = __float2bfloat16(a.x - __bfloat162float(h0.x));
        l0.y = __float2bfloat16(a.y - __bfloat162float(h0.y));
        l1.x = __float2bfloat16(a.z - __bfloat162float(h1.x));
        l1.y = __float2bfloat16(a.w - __bfloat162float(h1.y));
        reinterpret_cast<__nv_bfloat162*>(rf_h + row * DD)[2 * t] = h0;
        reinterpret_cast<__nv_bfloat162*>(rf_h + row * DD)[2 * t + 1] = h1;
        reinterpret_cast<__nv_bfloat162*>(rf_l + row * DD)[2 * t] = l0;
        reinterpret_cast<__nv_bfloat162*>(rf_l + row * DD)[2 * t + 1] = l1;

        float p = a.x * w.x + a.y * w.y + a.z * w.z + a.w * w.w;
        #pragma unroll
        for (int o = 16; o; o >>= 1) p += __shfl_xor_sync(0xffffffffu, p, o);
        if ((t & 31) == 0) red[t >> 5] = p;
        __syncthreads();
        if (t == 0) {
            float s = 0.f;
            #pragma unroll
            for (int i = 0; i < 8; i++) s += red[i];
            rd0[row] = s;
        }
    } else {
        size_t row = blockIdx.x - BB * RR;
        float4 a = *reinterpret_cast<const float4*>(query + row * DD + t * 4);
        float4 vv = *reinterpret_cast<const float4*>(v + t * 4);
        float4 w1 = *reinterpret_cast<const float4*>(Ws + DD + t * 4);
        float4 w2 = *reinterpret_cast<const float4*>(Ws + 2 * DD + t * 4);

        __nv_bfloat162 h0, h1, l0, l1;
        h0.x = __float2bfloat16(a.x); h0.y = __float2bfloat16(a.y);
        h1.x = __float2bfloat16(a.z); h1.y = __float2bfloat16(a.w);
        l0.x = __float2bfloat16(a.x - __bfloat162float(h0.x));
        l0.y = __float2bfloat16(a.y - __bfloat162float(h0.y));
        l1.x = __float2bfloat16(a.z - __bfloat162float(h1.x));
        l1.y = __float2bfloat16(a.w - __bfloat162float(h1.y));
        reinterpret_cast<__nv_bfloat162*>(qe_h + row * DD)[2 * t] = h0;
        reinterpret_cast<__nv_bfloat162*>(qe_h + row * DD)[2 * t + 1] = h1;
        reinterpret_cast<__nv_bfloat162*>(qe_l + row * DD)[2 * t] = l0;
        reinterpret_cast<__nv_bfloat162*>(qe_l + row * DD)[2 * t + 1] = l1;

        float b0 = a.x * w2.x, b1 = a.y * w2.y, b2 = a.z * w2.z, b3 = a.w * w2.w;
        h0.x = __float2bfloat16(b0); h0.y = __float2bfloat16(b1);
        h1.x = __float2bfloat16(b2); h1.y = __float2bfloat16(b3);
        l0.x = __float2bfloat16(b0 - __bfloat162float(h0.x));
        l0.y = __float2bfloat16(b1 - __bfloat162float(h0.y));
        l1.x = __float2bfloat16(b2 - __bfloat162float(h1.x));
        l1.y = __float2bfloat16(b3 - __bfloat162float(h1.y));
        reinterpret_cast<__nv_bfloat162*>(qe2_h + row * DD)[2 * t] = h0;
        reinterpret_cast<__nv_bfloat162*>(qe2_h + row * DD)[2 * t + 1] = h1;
        reinterpret_cast<__nv_bfloat162*>(qe2_l + row * DD)[2 * t] = l0;
        reinterpret_cast<__nv_bfloat162*>(qe2_l + row * DD)[2 * t + 1] = l1;

        float p = a.x * vv.x + a.y * vv.y + a.z * vv.z + a.w * vv.w;
        float q = a.x * w1.x + a.y * w1.y + a.z * w1.z + a.w * w1.w;
        #pragma unroll
        for (int o = 16; o; o >>= 1) {
            p += __shfl_xor_sync(0xffffffffu, p, o);
            q += __shfl_xor_sync(0xffffffffu, q, o);
        }
        if ((t & 31) == 0) { red[t >> 5] = p; red[8 + (t >> 5)] = q; }
        __syncthreads();
        if (t == 0) {
            float s = 0.f, s2 = 0.f;
            #pragma unroll
            for (int i = 0; i < 8; i++) { s += red[i]; s2 += red[8 + i]; }
            qv[row] = s;
            y1[row] = s2;
        }
    }
}

// ---------------------------------------------------------------------------
// v[d] = sum_h Wq[d,h] * br[h]
// ---------------------------------------------------------------------------
__global__ void __launch_bounds__(256) matvec_k(
    const float* __restrict__ W, const float* __restrict__ b,
    float* __restrict__ v, int H)
{
    const float* row = W + (size_t)blockIdx.x * H;
    int t = threadIdx.x;
    float p = 0.f;
    for (int h = t * 4; h < H; h += 1024) {
        float4 wv = *reinterpret_cast<const float4*>(row + h);
        float4 bv = *reinterpret_cast<const float4*>(b + h);
        p = fmaf(wv.x, bv.x, p); p = fmaf(wv.y, bv.y, p);
        p = fmaf(wv.z, bv.z, p); p = fmaf(wv.w, bv.w, p);
    }
    __shared__ float red[8];
    #pragma unroll
    for (int o = 16; o; o >>= 1) p += __shfl_xor_sync(0xffffffffu, p, o);
    if ((t & 31) == 0) red[t >> 5] = p;
    __syncthreads();
    if (t == 0) {
        float s = 0.f;
        #pragma unroll
        for (int i = 0; i < 8; i++) s += red[i];
        v[blockIdx.x] = s;
    }
}

// ---------------------------------------------------------------------------
extern "C" void kernel_launch(void* const* d_in, const int* in_sizes, int n_in,
                              void* d_out, int out_size)
{
    const float* region = (const float*)d_in[0];
    const float* query  = (const float*)d_in[1];
    const float* Wr     = (const float*)d_in[2];
    const float* br     = (const float*)d_in[3];
    const float* Wq     = (const float*)d_in[4];
    const float* bq     = (const float*)d_in[5];
    const float* Ws     = (const float*)d_in[6];
    const float* bs     = (const float*)d_in[7];
    float* out = (float*)d_out;
    (void)bq;  // softmax-invariant terms drop out

    __nv_bfloat16 *Wr_h, *Wr_l, *Wq_h, *Wq_l, *M2_h, *M2_l;
    __nv_bfloat16 *rf_h, *rf_l, *qe_h, *qe_l, *qe2_h, *qe2_l, *Nt_h, *Nt_l;
    float4 *partb;
    float *v, *qv, *y1, *rd0;
    cudaGetSymbolAddress((void**)&Wr_h, g_Wr_h);
    cudaGetSymbolAddress((void**)&Wr_l, g_Wr_l);
    cudaGetSymbolAddress((void**)&Wq_h, g_Wq_h);
    cudaGetSymbolAddress((void**)&Wq_l, g_Wq_l);
    cudaGetSymbolAddress((void**)&M2_h, g_M2_h);
    cudaGetSymbolAddress((void**)&M2_l, g_M2_l);
    cudaGetSymbolAddress((void**)&rf_h, g_rf_h);
    cudaGetSymbolAddress((void**)&rf_l, g_rf_l);
    cudaGetSymbolAddress((void**)&qe_h, g_qe_h);
    cudaGetSymbolAddress((void**)&qe_l, g_qe_l);
    cudaGetSymbolAddress((void**)&qe2_h, g_qe2_h);
    cudaGetSymbolAddress((void**)&qe2_l, g_qe2_l);
    cudaGetSymbolAddress((void**)&Nt_h, g_Nt_h);
    cudaGetSymbolAddress((void**)&Nt_l, g_Nt_l);
    cudaGetSymbolAddress((void**)&partb, g_part);
    cudaGetSymbolAddress((void**)&v, g_v);
    cudaGetSymbolAddress((void**)&qv, g_qv);
    cudaGetSymbolAddress((void**)&y1, g_y1);
    cudaGetSymbolAddress((void**)&rd0, g_rd0);

    const int SMEM1 = 2 * (2 * 8192 + 2 * 16384);       // 98304 (2-stage, 48KB) -> 2 CTAs/SM
    const int SMEMD = 2 * 8192 + 4 * 16384;             // 81920 (1-stage, 80KB) -> 2 CTAs/SM
    cudaFuncSetAttribute(gemm_mma1, cudaFuncAttributeMaxDynamicSharedMemorySize, SMEM1);
    cudaFuncSetAttribute(gemm_dual, cudaFuncAttributeMaxDynamicSharedMemorySize, SMEMD);

    // 1) merged weight splits + bias matvec
    split2w_k<<<1024, 256>>>((const float4*)Wr, (const float4*)Wq,
                             Wr_h, Wr_l, Wq_h, Wq_l);
    matvec_k<<<DD, 256>>>(Wq, br, v, HH);
    // 2) merged activation prep (region + query in one launch)
    prep_k<<<BB * RR + BB * TT, 256>>>(region, query, v, Ws,
                                       rf_h, rf_l, qe_h, qe_l, qe2_h, qe2_l,
                                       rd0, qv, y1);
    // 3) M2[d,e] = sum_h Wr[d,h] Wq[e,h]  (e contiguous), split output
    gemm_mma1<<<dim3(DD / 128, DD / 64, 1), 256, SMEM1>>>(
        Wr_h, Wr_l, Wq_h, Wq_l, M2_h, M2_l, HH, 0, 0, 0, DD);
    // 4) Nt[b][t,d] = sum_e qe[b,t,e] M2[d,e]  (d contiguous), split output
    gemm_mma1<<<dim3(DD / 128, TT / 64, BB), 256, SMEM1>>>(
        qe_h, qe_l, M2_h, M2_l, Nt_h, Nt_l,
        DD, (size_t)TT * DD, 0, (size_t)TT * DD, DD);
    // 5) dual GEMM (1-stage split-wait, 2 CTAs/SM) with fused softmax -> partials
    gemm_dual<<<dim3(TT / 128, RR / 64, BB), 256, SMEMD>>>(
        rf_h, rf_l, Nt_h, Nt_l, qe2_h, qe2_l, qv, y1, partb,
        DD, (size_t)RR * DD, (size_t)TT * DD);
    // 6) finalize: merge partials -> out
    finalize_k<<<BB * RR / 256, 256>>>(partb, rd0, bs, out);
}